// round 4
// baseline (speedup 1.0000x reference)
#include <cuda_runtime.h>
#include <math.h>
#include <stdint.h>

// Problem constants
#define Bb   4
#define Ss   2048
#define HIDn 1024
#define HEADS 16
#define HD   64
#define ROWS (Bb*Ss)          // 8192

// ---------------- scratch (device globals: allocation-guard safe) ----------
__device__ float g_Q[Bb*HEADS*Ss*HD];   // [B,H,S,D] (tf32-rounded)
__device__ float g_K[Bb*HEADS*Ss*HD];
__device__ float g_V[Bb*HEADS*Ss*HD];
__device__ float g_O[Bb*Ss*HIDn];       // [B,S,H*D] row-major (fp32)
__device__ float g_WT[HIDn*HIDn];       // transposed + tf32-rounded weight

// ============================================================================
// helpers
// ============================================================================
__device__ __forceinline__ uint32_t smem_u32(const void* p) {
    uint32_t a;
    asm("{ .reg .u64 t; cvta.to.shared.u64 t, %1; cvt.u32.u64 %0, t; }"
        : "=r"(a) : "l"(p));
    return a;
}
__device__ __forceinline__ uint32_t f2tf(float x) {
    uint32_t u;
    asm("cvt.rna.tf32.f32 %0, %1;" : "=r"(u) : "f"(x));
    return u;
}
__device__ __forceinline__ float tf32r(float x) { return __uint_as_float(f2tf(x)); }

__device__ __forceinline__ void mma8(float& d0, float& d1, float& d2, float& d3,
                                     uint32_t a0, uint32_t a1, uint32_t a2, uint32_t a3,
                                     uint32_t b0, uint32_t b1) {
    asm volatile(
        "mma.sync.aligned.m16n8k8.row.col.f32.tf32.tf32.f32 "
        "{%0,%1,%2,%3}, {%4,%5,%6,%7}, {%8,%9}, {%0,%1,%2,%3};"
        : "+f"(d0), "+f"(d1), "+f"(d2), "+f"(d3)
        : "r"(a0), "r"(a1), "r"(a2), "r"(a3), "r"(b0), "r"(b1));
}
__device__ __forceinline__ void cp16(uint32_t s, const void* g) {
    asm volatile("cp.async.cg.shared.global [%0], [%1], 16;" :: "r"(s), "l"(g));
}
#define CP_COMMIT() asm volatile("cp.async.commit_group;" ::: "memory")
#define CP_WAIT1()  asm volatile("cp.async.wait_group 1;"  ::: "memory")

// ============================================================================
// Weight transpose + tf32 rounding: WT[n][k] = tf32(W[k][n])
// ============================================================================
__global__ __launch_bounds__(256)
void transpose1024(const float* __restrict__ in, float* __restrict__ out)
{
    __shared__ float t[32][33];
    int x = blockIdx.x * 32 + threadIdx.x;
    int y0 = blockIdx.y * 32;
    #pragma unroll
    for (int l = 0; l < 32; l += 8)
        t[threadIdx.y + l][threadIdx.x] = in[(size_t)(y0 + threadIdx.y + l) * 1024 + x];
    __syncthreads();
    int xo = blockIdx.y * 32 + threadIdx.x;
    int yo = blockIdx.x * 32;
    #pragma unroll
    for (int l = 0; l < 32; l += 8)
        out[(size_t)(yo + threadIdx.y + l) * 1024 + xo] = tf32r(t[threadIdx.x][threadIdx.y + l]);
}

// ============================================================================
// tf32 mma.sync GEMM: C = A[M,1024] * W[1024,N] + bias,  W pre-transposed
// (WT[N,1024], K-major, tf32-rounded). 128x128 tile/CTA, BK=64, 3-stage
// cp.async. 8 warps, warp tile 64x32 (wm=wid&1, wn=wid>>1).
// MODE 0: C row-major [M,N] fp32.  MODE 1: scatter to [B,H,S,D], tf32-rounded.
// ============================================================================
#define GSTAGES 3
#define GASTR   68
#define GSTG    (128*GASTR)            // floats per stage per tensor
#define GEMM_SMEM (2*GSTAGES*GSTG*4)   // 208896 bytes

template<int MODE>
__global__ __launch_bounds__(256, 1)
void gemm_tc(const float* __restrict__ A, const float* __restrict__ WT,
             const float* __restrict__ bias, float* __restrict__ C)
{
    extern __shared__ float smf[];
    float* As = smf;                    // [3][128][68]
    float* Bs = smf + GSTAGES * GSTG;   // [3][128][68]
    const uint32_t sA = smem_u32(As);
    const uint32_t sB = smem_u32(Bs);

    const int tid  = threadIdx.x;
    const int wid  = tid >> 5;
    const int lane = tid & 31;
    const int gr   = lane >> 2;
    const int tc   = lane & 3;
    const int wm   = wid & 1;          // 2 row groups of 64
    const int wn   = wid >> 1;         // 4 col groups of 32
    const int row0 = blockIdx.y * 128;
    const int col0 = blockIdx.x * 128;

    const float* Ag0 = A  + (size_t)row0 * 1024;
    const float* Bg0 = WT + (size_t)col0 * 1024;

    float acc[4][4][4];
    #pragma unroll
    for (int mt = 0; mt < 4; mt++)
        #pragma unroll
        for (int nt = 0; nt < 4; nt++)
            #pragma unroll
            for (int e = 0; e < 4; e++) acc[mt][nt][e] = 0.f;

    // stage loader: 128 rows x 64 floats each for A and B (8 cp16/tensor/thr)
    const int lr  = tid >> 4;          // 0..15
    const int lc4 = (tid & 15) << 2;   // 0..60 step 4
    #define LOAD_STAGE(st, chunk) do {                                         \
        const float* _Ag = Ag0 + (chunk) * 64;                                 \
        const float* _Bg = Bg0 + (chunk) * 64;                                 \
        uint32_t _aS = sA + (st) * GSTG * 4;                                   \
        uint32_t _bS = sB + (st) * GSTG * 4;                                   \
        _Pragma("unroll")                                                      \
        for (int l = 0; l < 8; l++) {                                          \
            int r = lr + l * 16;                                               \
            cp16(_aS + (r * GASTR + lc4) * 4, _Ag + (size_t)r * 1024 + lc4);   \
            cp16(_bS + (r * GASTR + lc4) * 4, _Bg + (size_t)r * 1024 + lc4);   \
        }                                                                      \
    } while (0)

    LOAD_STAGE(0, 0); CP_COMMIT();
    LOAD_STAGE(1, 1); CP_COMMIT();

    for (int i = 0; i < 16; i++) {
        const int s = i % 3;
        CP_WAIT1();
        __syncthreads();

        // issue prefetch for chunk i+2 before compute (stage (i+2)%3 is free)
        const int j = i + 2;
        if (j < 16) { LOAD_STAGE(j % 3, j); }
        CP_COMMIT();

        const float* Asb = As + s * GSTG;
        const float* Bsb = Bs + s * GSTG;

        #pragma unroll
        for (int ks = 0; ks < 8; ks++) {
            const int k0 = ks * 8;
            uint32_t a[4][4], b[4][2];
            #pragma unroll
            for (int mt = 0; mt < 4; mt++) {
                const float* p = Asb + (wm * 64 + mt * 16 + gr) * GASTR + k0 + tc;
                a[mt][0] = f2tf(p[0]);
                a[mt][1] = f2tf(p[8 * GASTR]);
                a[mt][2] = f2tf(p[4]);
                a[mt][3] = f2tf(p[8 * GASTR + 4]);
            }
            #pragma unroll
            for (int nt = 0; nt < 4; nt++) {
                const float* p = Bsb + (wn * 32 + nt * 8 + gr) * GASTR + k0 + tc;
                b[nt][0] = __float_as_uint(p[0]);   // pre-rounded
                b[nt][1] = __float_as_uint(p[4]);
            }
            #pragma unroll
            for (int mt = 0; mt < 4; mt++)
                #pragma unroll
                for (int nt = 0; nt < 4; nt++)
                    mma8(acc[mt][nt][0], acc[mt][nt][1], acc[mt][nt][2], acc[mt][nt][3],
                         a[mt][0], a[mt][1], a[mt][2], a[mt][3], b[nt][0], b[nt][1]);
        }
    }

    // ---- epilogue ----
    #pragma unroll
    for (int mt = 0; mt < 4; mt++) {
        const int r0 = row0 + wm * 64 + mt * 16 + gr;
        #pragma unroll
        for (int nt = 0; nt < 4; nt++) {
            const int c = col0 + wn * 32 + nt * 8 + 2 * tc;
            const float2 bi = *(const float2*)(bias + c);
            float v00 = acc[mt][nt][0] + bi.x, v01 = acc[mt][nt][1] + bi.y;
            float v10 = acc[mt][nt][2] + bi.x, v11 = acc[mt][nt][3] + bi.y;
            if (MODE == 1) {
                v00 = tf32r(v00); v01 = tf32r(v01);
                v10 = tf32r(v10); v11 = tf32r(v11);
            }
            if (MODE == 0) {
                *(float2*)(C + (size_t)r0 * 1024 + c)       = make_float2(v00, v01);
                *(float2*)(C + (size_t)(r0 + 8) * 1024 + c) = make_float2(v10, v11);
            } else {
                const int h = c >> 6, d = c & 63;
                {
                    const int b = r0 >> 11, s_ = r0 & 2047;
                    *(float2*)(C + ((((size_t)(b * HEADS + h)) * Ss + s_) * HD + d))
                        = make_float2(v00, v01);
                }
                {
                    const int r1 = r0 + 8;
                    const int b = r1 >> 11, s_ = r1 & 2047;
                    *(float2*)(C + ((((size_t)(b * HEADS + h)) * Ss + s_) * HD + d))
                        = make_float2(v10, v11);
                }
            }
        }
    }
}

// ============================================================================
// Flash attention with tf32 mma.sync + cp.async K/V prefetch + 256-thread
// softmax. Block = (bh, 128-query tile), 256 threads / 8 warps.
// QK warp tile 64x32 (wmq=wid&1, wnq=wid>>1); PV warp tile 32x32
// (wmp=wid&3, wnp=wid>>2).
// Strides: Q/K 68, V 72 (PV B-frags fully conflict-free), P 133.
// ============================================================================
#define AQSTR 68
#define AVSTR 72
#define APSTR 133
#define ATT_SMEM_FLOATS (2*128*AQSTR + 128*AVSTR + 128*APSTR + 3*128)
#define ATT_SMEM_BYTES  (ATT_SMEM_FLOATS * 4)

__global__ __launch_bounds__(256, 1)
void attn_kernel()
{
    extern __shared__ float sm[];
    float* Qs   = sm;                      // 128*68
    float* Ks   = Qs + 128 * AQSTR;        // 128*68
    float* Vs   = Ks + 128 * AQSTR;        // 128*72
    float* Ps   = Vs + 128 * AVSTR;        // 128*133
    float* mrow = Ps + 128 * APSTR;
    float* lrow = mrow + 128;
    float* crow = lrow + 128;
    const uint32_t sKs = smem_u32(Ks);
    const uint32_t sVs = smem_u32(Vs);

    const int bh   = blockIdx.y;
    const int qt   = blockIdx.x;
    const int tid  = threadIdx.x;
    const int wid  = tid >> 5;
    const int lane = tid & 31;
    const int gr   = lane >> 2;
    const int tc   = lane & 3;
    const int wmq  = wid & 1,  wnq = wid >> 1;   // QK: 64x32
    const int wmp  = wid & 3,  wnp = wid >> 2;   // PV: 32x32

    const float* Qg = g_Q + (size_t)bh * Ss * HD + (size_t)qt * 128 * HD;
    const float* Kg = g_K + (size_t)bh * Ss * HD;
    const float* Vg = g_V + (size_t)bh * Ss * HD;

    const int flr = tid >> 4;              // 0..15
    const int flc = (tid & 15) << 2;       // 0..60
    #define LOAD_KT(kt) do {                                                   \
        const float* _Kt = Kg + (size_t)(kt) * 128 * HD;                       \
        _Pragma("unroll")                                                      \
        for (int l = 0; l < 8; l++) {                                          \
            int r = flr + l * 16;                                              \
            cp16(sKs + (r * AQSTR + flc) * 4, _Kt + (size_t)r * HD + flc);     \
        }                                                                      \
    } while (0)
    #define LOAD_VT(kt) do {                                                   \
        const float* _Vt = Vg + (size_t)(kt) * 128 * HD;                       \
        _Pragma("unroll")                                                      \
        for (int l = 0; l < 8; l++) {                                          \
            int r = flr + l * 16;                                              \
            cp16(sVs + (r * AVSTR + flc) * 4, _Vt + (size_t)r * HD + flc);     \
        }                                                                      \
    } while (0)

    // prefetch first K/V tiles
    LOAD_KT(0); CP_COMMIT();
    LOAD_VT(0); CP_COMMIT();

    // load Q tile (128x64) into stride-68 smem
    for (int f = tid; f < 2048; f += 256) {
        int r  = f >> 4;
        int c4 = (f & 15) << 2;
        float4 v = *(const float4*)(Qg + (size_t)r * HD + c4);
        float* q = Qs + r * AQSTR + c4;
        q[0] = v.x; q[1] = v.y; q[2] = v.z; q[3] = v.w;
    }
    if (tid < 128) { mrow[tid] = -1e30f; lrow[tid] = 0.f; }

    float o[2][4][4];
    #pragma unroll
    for (int mt = 0; mt < 2; mt++)
        #pragma unroll
        for (int nt = 0; nt < 4; nt++)
            #pragma unroll
            for (int e = 0; e < 4; e++) o[mt][nt][e] = 0.f;

    for (int kt = 0; kt < 16; kt++) {
        CP_WAIT1();          // K(kt) landed (V(kt) may still be in flight)
        __syncthreads();     // K visible to all; prev iter fully done; Q ready

        // ---- S = Q K^T (K=64, 8 ksteps), warp tile 64x32 ----
        float sacc[4][4][4];
        #pragma unroll
        for (int mt = 0; mt < 4; mt++)
            #pragma unroll
            for (int nt = 0; nt < 4; nt++)
                #pragma unroll
                for (int e = 0; e < 4; e++) sacc[mt][nt][e] = 0.f;

        #pragma unroll
        for (int ks = 0; ks < 8; ks++) {
            const int k0 = ks * 8;
            uint32_t a[4][4], b[4][2];
            #pragma unroll
            for (int mt = 0; mt < 4; mt++) {
                const float* p = Qs + (wmq * 64 + mt * 16 + gr) * AQSTR + k0 + tc;
                a[mt][0] = __float_as_uint(p[0]);
                a[mt][1] = __float_as_uint(p[8 * AQSTR]);
                a[mt][2] = __float_as_uint(p[4]);
                a[mt][3] = __float_as_uint(p[8 * AQSTR + 4]);
            }
            #pragma unroll
            for (int nt = 0; nt < 4; nt++) {
                const float* p = Ks + (wnq * 32 + nt * 8 + gr) * AQSTR + k0 + tc;
                b[nt][0] = __float_as_uint(p[0]);
                b[nt][1] = __float_as_uint(p[4]);
            }
            #pragma unroll
            for (int mt = 0; mt < 4; mt++)
                #pragma unroll
                for (int nt = 0; nt < 4; nt++)
                    mma8(sacc[mt][nt][0], sacc[mt][nt][1], sacc[mt][nt][2], sacc[mt][nt][3],
                         a[mt][0], a[mt][1], a[mt][2], a[mt][3], b[nt][0], b[nt][1]);
        }

        // store S*scale to Ps
        #pragma unroll
        for (int mt = 0; mt < 4; mt++) {
            const int r0 = wmq * 64 + mt * 16 + gr;
            #pragma unroll
            for (int nt = 0; nt < 4; nt++) {
                const int c = wnq * 32 + nt * 8 + 2 * tc;
                Ps[r0 * APSTR + c]           = sacc[mt][nt][0] * 0.125f;
                Ps[r0 * APSTR + c + 1]       = sacc[mt][nt][1] * 0.125f;
                Ps[(r0 + 8) * APSTR + c]     = sacc[mt][nt][2] * 0.125f;
                Ps[(r0 + 8) * APSTR + c + 1] = sacc[mt][nt][3] * 0.125f;
            }
        }
        __syncthreads();     // S complete; Ks free

        if (kt < 15) { LOAD_KT(kt + 1); }   // overlaps softmax + PV
        CP_COMMIT();

        // ---- online softmax: 256 threads, half-row each, pair shfl ----
        {
            const int r = tid >> 1;
            const int h = tid & 1;
            float* pr = Ps + r * APSTR + h * 64;
            float mloc = -1e30f;
            #pragma unroll 4
            for (int i = 0; i < 64; i++) mloc = fmaxf(mloc, pr[i ^ h]);
            mloc = fmaxf(mloc, __shfl_xor_sync(0xFFFFFFFFu, mloc, 1));
            const float mold = mrow[r];
            const float mx = fmaxf(mold, mloc);
            float sum = 0.f;
            #pragma unroll 4
            for (int i = 0; i < 64; i++) {
                const int k = i ^ h;
                float p = __expf(pr[k] - mx);
                sum += p;
                pr[k] = tf32r(p);
            }
            sum += __shfl_xor_sync(0xFFFFFFFFu, sum, 1);
            if (h == 0) {
                const float corr = __expf(mold - mx);
                mrow[r] = mx;
                lrow[r] = lrow[r] * corr + sum;
                crow[r] = corr;
            }
        }
        CP_WAIT1();          // V(kt) landed (K(kt+1) may still be in flight)
        __syncthreads();     // softmax + V visible

        // ---- rescale o, then o += P V (K=128, 16 ksteps), warp tile 32x32 ----
        #pragma unroll
        for (int mt = 0; mt < 2; mt++) {
            const int r0 = wmp * 32 + mt * 16 + gr;
            const float c0 = crow[r0];
            const float c1 = crow[r0 + 8];
            #pragma unroll
            for (int nt = 0; nt < 4; nt++) {
                o[mt][nt][0] *= c0; o[mt][nt][1] *= c0;
                o[mt][nt][2] *= c1; o[mt][nt][3] *= c1;
            }
        }
        #pragma unroll 4
        for (int ks = 0; ks < 16; ks++) {
            const int k0 = ks * 8;
            uint32_t a[2][4], b[4][2];
            #pragma unroll
            for (int mt = 0; mt < 2; mt++) {
                const float* p = Ps + (wmp * 32 + mt * 16 + gr) * APSTR + k0 + tc;
                a[mt][0] = __float_as_uint(p[0]);
                a[mt][1] = __float_as_uint(p[8 * APSTR]);
                a[mt][2] = __float_as_uint(p[4]);
                a[mt][3] = __float_as_uint(p[8 * APSTR + 4]);
            }
            #pragma unroll
            for (int nt = 0; nt < 4; nt++) {
                const float* p = Vs + (k0 + tc) * AVSTR + wnp * 32 + nt * 8 + gr;
                b[nt][0] = __float_as_uint(p[0]);
                b[nt][1] = __float_as_uint(p[4 * AVSTR]);
            }
            #pragma unroll
            for (int mt = 0; mt < 2; mt++)
                #pragma unroll
                for (int nt = 0; nt < 4; nt++)
                    mma8(o[mt][nt][0], o[mt][nt][1], o[mt][nt][2], o[mt][nt][3],
                         a[mt][0], a[mt][1], a[mt][2], a[mt][3], b[nt][0], b[nt][1]);
        }
        __syncthreads();     // PV done; Vs free

        if (kt < 15) { LOAD_VT(kt + 1); }   // overlaps next QK + softmax
        CP_COMMIT();
    }

    // ---- normalize + store to g_O [B,S,H*D] ----
    const int b = bh >> 4;
    const int h = bh & 15;
    #pragma unroll
    for (int mt = 0; mt < 2; mt++) {
        const int r0 = wmp * 32 + mt * 16 + gr;
        const float i0 = 1.0f / lrow[r0];
        const float i1 = 1.0f / lrow[r0 + 8];
        #pragma unroll
        for (int nt = 0; nt < 4; nt++) {
            const int c = wnp * 32 + nt * 8 + 2 * tc;   // d index
            {
                const int s_ = qt * 128 + r0;
                size_t idx = ((size_t)(b * Ss + s_)) * HIDn + h * HD + c;
                *(float2*)(g_O + idx) = make_float2(o[mt][nt][0] * i0, o[mt][nt][1] * i0);
            }
            {
                const int s_ = qt * 128 + r0 + 8;
                size_t idx = ((size_t)(b * Ss + s_)) * HIDn + h * HD + c;
                *(float2*)(g_O + idx) = make_float2(o[mt][nt][2] * i1, o[mt][nt][3] * i1);
            }
        }
    }
}

// ============================================================================
// launch
// ============================================================================
extern "C" void kernel_launch(void* const* d_in, const int* in_sizes, int n_in,
                              void* d_out, int out_size)
{
    (void)in_sizes; (void)n_in; (void)out_size;
    const float* q  = (const float*)d_in[0];
    const float* k  = (const float*)d_in[1];
    const float* v  = (const float*)d_in[2];
    const float* wq = (const float*)d_in[3];
    const float* bq = (const float*)d_in[4];
    const float* wk = (const float*)d_in[5];
    const float* bk = (const float*)d_in[6];
    const float* wv = (const float*)d_in[7];
    const float* bv = (const float*)d_in[8];
    const float* wo = (const float*)d_in[9];
    const float* bo = (const float*)d_in[10];
    float* out = (float*)d_out;

    float *Qp, *Kp, *Vp, *Op, *WTp;
    cudaGetSymbolAddress((void**)&Qp,  g_Q);
    cudaGetSymbolAddress((void**)&Kp,  g_K);
    cudaGetSymbolAddress((void**)&Vp,  g_V);
    cudaGetSymbolAddress((void**)&Op,  g_O);
    cudaGetSymbolAddress((void**)&WTp, g_WT);

    cudaFuncSetAttribute(attn_kernel,
                         cudaFuncAttributeMaxDynamicSharedMemorySize, ATT_SMEM_BYTES);
    cudaFuncSetAttribute(gemm_tc<0>,
                         cudaFuncAttributeMaxDynamicSharedMemorySize, GEMM_SMEM);
    cudaFuncSetAttribute(gemm_tc<1>,
                         cudaFuncAttributeMaxDynamicSharedMemorySize, GEMM_SMEM);

    dim3 tgrid(32, 32), tblk(32, 8);
    dim3 ggrid(HIDn / 128, ROWS / 128);   // (8, 64)

    transpose1024<<<tgrid, tblk>>>(wq, WTp);
    gemm_tc<1><<<ggrid, 256, GEMM_SMEM>>>(q, WTp, bq, Qp);
    transpose1024<<<tgrid, tblk>>>(wk, WTp);
    gemm_tc<1><<<ggrid, 256, GEMM_SMEM>>>(k, WTp, bk, Kp);
    transpose1024<<<tgrid, tblk>>>(wv, WTp);
    gemm_tc<1><<<ggrid, 256, GEMM_SMEM>>>(v, WTp, bv, Vp);

    attn_kernel<<<dim3(Ss / 128, Bb * HEADS), 256, ATT_SMEM_BYTES>>>();

    transpose1024<<<tgrid, tblk>>>(wo, WTp);
    gemm_tc<0><<<ggrid, 256, GEMM_SMEM>>>(Op, WTp, bo, out);
}

// round 5
// speedup vs baseline: 1.5948x; 1.5948x over previous
#include <cuda_runtime.h>
#include <math.h>
#include <stdint.h>

// Problem constants
#define Bb   4
#define Ss   2048
#define HIDn 1024
#define HEADS 16
#define HD   64
#define ROWS (Bb*Ss)          // 8192

// ---------------- scratch (device globals: allocation-guard safe) ----------
__device__ float g_Q[Bb*HEADS*Ss*HD];   // [B,H,S,D] (tf32-rounded)
__device__ float g_K[Bb*HEADS*Ss*HD];
__device__ float g_V[Bb*HEADS*Ss*HD];
__device__ float g_O[Bb*Ss*HIDn];       // [B,S,H*D] row-major (fp32)
__device__ float g_WT[HIDn*HIDn];       // transposed + tf32-rounded weight

// ============================================================================
// helpers
// ============================================================================
__device__ __forceinline__ uint32_t smem_u32(const void* p) {
    uint32_t a;
    asm("{ .reg .u64 t; cvta.to.shared.u64 t, %1; cvt.u32.u64 %0, t; }"
        : "=r"(a) : "l"(p));
    return a;
}
__device__ __forceinline__ uint32_t f2tf(float x) {
    uint32_t u;
    asm("cvt.rna.tf32.f32 %0, %1;" : "=r"(u) : "f"(x));
    return u;
}
__device__ __forceinline__ float tf32r(float x) { return __uint_as_float(f2tf(x)); }

__device__ __forceinline__ void mma8(float& d0, float& d1, float& d2, float& d3,
                                     uint32_t a0, uint32_t a1, uint32_t a2, uint32_t a3,
                                     uint32_t b0, uint32_t b1) {
    asm volatile(
        "mma.sync.aligned.m16n8k8.row.col.f32.tf32.tf32.f32 "
        "{%0,%1,%2,%3}, {%4,%5,%6,%7}, {%8,%9}, {%0,%1,%2,%3};"
        : "+f"(d0), "+f"(d1), "+f"(d2), "+f"(d3)
        : "r"(a0), "r"(a1), "r"(a2), "r"(a3), "r"(b0), "r"(b1));
}
__device__ __forceinline__ void ldm4(uint32_t& r0, uint32_t& r1, uint32_t& r2,
                                     uint32_t& r3, uint32_t addr) {
    asm volatile("ldmatrix.sync.aligned.m8n8.x4.shared.b16 {%0,%1,%2,%3}, [%4];"
                 : "=r"(r0), "=r"(r1), "=r"(r2), "=r"(r3) : "r"(addr));
}
__device__ __forceinline__ void cp16(uint32_t s, const void* g) {
    asm volatile("cp.async.cg.shared.global [%0], [%1], 16;" :: "r"(s), "l"(g));
}
#define CP_COMMIT() asm volatile("cp.async.commit_group;" ::: "memory")
#define CP_WAIT1()  asm volatile("cp.async.wait_group 1;"  ::: "memory")
#define CP_WAIT0()  asm volatile("cp.async.wait_group 0;"  ::: "memory")

// ============================================================================
// Weight transpose + tf32 rounding: WT[n][k] = tf32(W[k][n])
// ============================================================================
__global__ __launch_bounds__(256)
void transpose1024(const float* __restrict__ in, float* __restrict__ out)
{
    __shared__ float t[32][33];
    int x = blockIdx.x * 32 + threadIdx.x;
    int y0 = blockIdx.y * 32;
    #pragma unroll
    for (int l = 0; l < 32; l += 8)
        t[threadIdx.y + l][threadIdx.x] = in[(size_t)(y0 + threadIdx.y + l) * 1024 + x];
    __syncthreads();
    int xo = blockIdx.y * 32 + threadIdx.x;
    int yo = blockIdx.x * 32;
    #pragma unroll
    for (int l = 0; l < 32; l += 8)
        out[(size_t)(yo + threadIdx.y + l) * 1024 + xo] = tf32r(t[threadIdx.x][threadIdx.y + l]);
}

// ============================================================================
// tf32 mma.sync GEMM: C = A[M,1024] * W[1024,N] + bias,  W pre-transposed
// (WT[N,1024], K-major, tf32-rounded). 128x128 tile/CTA, BK=32, 3-stage
// cp.async, ldmatrix fragment loads, 2 CTAs/SM.
// 8 warps, warp tile 64x32 (wm=wid&1, wn=wid>>1).
// MODE 0: C row-major [M,N] fp32.  MODE 1: scatter to [B,H,S,D], tf32-rounded.
// ============================================================================
#define GSTAGES 3
#define GASTR   36
#define GSTG    (128*GASTR)            // floats per stage per tensor
#define GSTGB   (GSTG*4)               // bytes per stage
#define GEMM_SMEM (2*GSTAGES*GSTGB)    // 110592 bytes

template<int MODE>
__global__ __launch_bounds__(256, 2)
void gemm_tc(const float* __restrict__ A, const float* __restrict__ WT,
             const float* __restrict__ bias, float* __restrict__ C)
{
    extern __shared__ float smf[];
    float* As = smf;                    // [3][128][36]
    float* Bs = smf + GSTAGES * GSTG;   // [3][128][36]
    const uint32_t sA = smem_u32(As);
    const uint32_t sB = smem_u32(Bs);

    const int tid  = threadIdx.x;
    const int wid  = tid >> 5;
    const int lane = tid & 31;
    const int gr   = lane >> 2;
    const int tc   = lane & 3;
    const int m8   = lane >> 3;
    const int e8   = lane & 7;
    const int wm   = wid & 1;          // 2 row groups of 64
    const int wn   = wid >> 1;         // 4 col groups of 32
    const int row0 = blockIdx.y * 128;
    const int col0 = blockIdx.x * 128;

    const float* Ag0 = A  + (size_t)row0 * 1024;
    const float* Bg0 = WT + (size_t)col0 * 1024;

    // ldmatrix lane offsets (bytes within a stage)
    uint32_t aOff[4], bOff[2];
    #pragma unroll
    for (int mt = 0; mt < 4; mt++)
        aOff[mt] = (uint32_t)(((wm * 64 + mt * 16 + e8 + ((m8 & 1) << 3)) * GASTR
                               + ((m8 >> 1) << 2)) << 2);
    #pragma unroll
    for (int p = 0; p < 2; p++)
        bOff[p] = (uint32_t)(((wn * 32 + p * 16 + ((m8 >> 1) << 3) + e8) * GASTR
                              + ((m8 & 1) << 2)) << 2);

    float acc[4][4][4];
    #pragma unroll
    for (int mt = 0; mt < 4; mt++)
        #pragma unroll
        for (int nt = 0; nt < 4; nt++)
            #pragma unroll
            for (int e = 0; e < 4; e++) acc[mt][nt][e] = 0.f;

    // stage loader: 128 rows x 32 floats each for A and B
    const int lr  = tid >> 3;          // 0..31
    const int lc4 = (tid & 7) << 2;    // 0..28
    #define LOAD_STAGE(st, chunk) do {                                         \
        const float* _Ag = Ag0 + (chunk) * 32;                                 \
        const float* _Bg = Bg0 + (chunk) * 32;                                 \
        uint32_t _aS = sA + (st) * GSTGB;                                      \
        uint32_t _bS = sB + (st) * GSTGB;                                      \
        _Pragma("unroll")                                                      \
        for (int l = 0; l < 4; l++) {                                          \
            int r = lr + l * 32;                                               \
            cp16(_aS + (r * GASTR + lc4) * 4, _Ag + (size_t)r * 1024 + lc4);   \
            cp16(_bS + (r * GASTR + lc4) * 4, _Bg + (size_t)r * 1024 + lc4);   \
        }                                                                      \
    } while (0)

    LOAD_STAGE(0, 0); CP_COMMIT();
    LOAD_STAGE(1, 1); CP_COMMIT();

    for (int i = 0; i < 32; i++) {
        const int s = i % 3;
        CP_WAIT1();
        __syncthreads();

        const int j = i + 2;
        if (j < 32) { LOAD_STAGE(j % 3, j); }
        CP_COMMIT();

        const uint32_t aBs = sA + s * GSTGB;
        const uint32_t bBs = sB + s * GSTGB;

        #pragma unroll
        for (int ks = 0; ks < 4; ks++) {
            uint32_t a[4][4], b[4][2];
            #pragma unroll
            for (int mt = 0; mt < 4; mt++) {
                ldm4(a[mt][0], a[mt][1], a[mt][2], a[mt][3], aBs + aOff[mt] + ks * 32);
                a[mt][0] = f2tf(__uint_as_float(a[mt][0]));
                a[mt][1] = f2tf(__uint_as_float(a[mt][1]));
                a[mt][2] = f2tf(__uint_as_float(a[mt][2]));
                a[mt][3] = f2tf(__uint_as_float(a[mt][3]));
            }
            #pragma unroll
            for (int p = 0; p < 2; p++) {
                uint32_t t0, t1, t2, t3;
                ldm4(t0, t1, t2, t3, bBs + bOff[p] + ks * 32);
                b[2 * p][0]     = t0; b[2 * p][1]     = t1;
                b[2 * p + 1][0] = t2; b[2 * p + 1][1] = t3;
            }
            #pragma unroll
            for (int mt = 0; mt < 4; mt++)
                #pragma unroll
                for (int nt = 0; nt < 4; nt++)
                    mma8(acc[mt][nt][0], acc[mt][nt][1], acc[mt][nt][2], acc[mt][nt][3],
                         a[mt][0], a[mt][1], a[mt][2], a[mt][3], b[nt][0], b[nt][1]);
        }
    }

    // ---- epilogue ----
    #pragma unroll
    for (int mt = 0; mt < 4; mt++) {
        const int r0 = row0 + wm * 64 + mt * 16 + gr;
        #pragma unroll
        for (int nt = 0; nt < 4; nt++) {
            const int c = col0 + wn * 32 + nt * 8 + 2 * tc;
            const float2 bi = *(const float2*)(bias + c);
            float v00 = acc[mt][nt][0] + bi.x, v01 = acc[mt][nt][1] + bi.y;
            float v10 = acc[mt][nt][2] + bi.x, v11 = acc[mt][nt][3] + bi.y;
            if (MODE == 1) {
                v00 = tf32r(v00); v01 = tf32r(v01);
                v10 = tf32r(v10); v11 = tf32r(v11);
            }
            if (MODE == 0) {
                *(float2*)(C + (size_t)r0 * 1024 + c)       = make_float2(v00, v01);
                *(float2*)(C + (size_t)(r0 + 8) * 1024 + c) = make_float2(v10, v11);
            } else {
                const int h = c >> 6, d = c & 63;
                {
                    const int b = r0 >> 11, s_ = r0 & 2047;
                    *(float2*)(C + ((((size_t)(b * HEADS + h)) * Ss + s_) * HD + d))
                        = make_float2(v00, v01);
                }
                {
                    const int r1 = r0 + 8;
                    const int b = r1 >> 11, s_ = r1 & 2047;
                    *(float2*)(C + ((((size_t)(b * HEADS + h)) * Ss + s_) * HD + d))
                        = make_float2(v10, v11);
                }
            }
        }
    }
}

// ============================================================================
// Flash attention, FA2-style: warp owns 16 query rows end-to-end.
// Block = (bh, 128-query tile), 256 threads / 8 warps, 2 CTAs/SM.
// Q fragments persistent in registers; S/P in registers; softmax via quad
// shuffles; P->A-fragment conversion via in-quad shfl.idx.
// smem: bufA (Q staging / K odd) 128x68, bufB (K even) 128x68, V 128x72.
// K double-buffered cp.async; V prefetched cp.async (hazard-safe: issued
// right after the top barrier which follows all PV reads of the old tile).
// ============================================================================
#define AKSTR 68
#define AVSTR 72
#define ATT_SMEM_FLOATS (2*128*AKSTR + 128*AVSTR)
#define ATT_SMEM_BYTES  (ATT_SMEM_FLOATS * 4)

__global__ __launch_bounds__(256, 2)
void attn_kernel()
{
    extern __shared__ float sm[];
    float* bufA = sm;                       // Q staging, then K for odd kt
    float* bufB = sm + 128 * AKSTR;         // K for even kt
    float* Vs   = sm + 2 * 128 * AKSTR;     // V tile
    const uint32_t sA = smem_u32(bufA);
    const uint32_t sBf = smem_u32(bufB);
    const uint32_t sV  = smem_u32(Vs);

    const int bh   = blockIdx.y;
    const int qt   = blockIdx.x;
    const int tid  = threadIdx.x;
    const int wid  = tid >> 5;
    const int lane = tid & 31;
    const int gr   = lane >> 2;
    const int tc   = lane & 3;
    const int m8   = lane >> 3;
    const int e8   = lane & 7;

    const float* Qg = g_Q + (size_t)bh * Ss * HD + (size_t)qt * 128 * HD;
    const float* Kg = g_K + (size_t)bh * Ss * HD;
    const float* Vg = g_V + (size_t)bh * Ss * HD;

    const int flr = tid >> 4;               // 0..15
    const int flc = (tid & 15) << 2;        // 0..60

    // issue K(0) -> bufB
    {
        #pragma unroll
        for (int l = 0; l < 8; l++) {
            int r = flr + l * 16;
            cp16(sBf + (r * AKSTR + flc) * 4, Kg + (size_t)r * HD + flc);
        }
    }
    CP_COMMIT();

    // stage Q into bufA (plain loads/stores)
    for (int f = tid; f < 2048; f += 256) {
        int r  = f >> 4;
        int c4 = (f & 15) << 2;
        float4 v = *(const float4*)(Qg + (size_t)r * HD + c4);
        float* q = bufA + r * AKSTR + c4;
        q[0] = v.x; q[1] = v.y; q[2] = v.z; q[3] = v.w;
    }
    __syncthreads();

    // extract persistent Q fragments (rows wid*16 .. wid*16+15)
    uint32_t qf[8][4];
    {
        const uint32_t qbase = sA + (uint32_t)(((wid * 16 + e8 + ((m8 & 1) << 3)) * AKSTR
                                                + ((m8 >> 1) << 2)) << 2);
        #pragma unroll
        for (int ks = 0; ks < 8; ks++)
            ldm4(qf[ks][0], qf[ks][1], qf[ks][2], qf[ks][3], qbase + ks * 32);
    }

    // K-fragment lane offsets (within a K buffer), per nt-pair p
    uint32_t kOff[4];
    #pragma unroll
    for (int p = 0; p < 4; p++)
        kOff[p] = (uint32_t)(((p * 16 + ((m8 >> 1) << 3) + e8) * AKSTR
                              + ((m8 & 1) << 2)) << 2);

    float m0 = -1e30f, m1 = -1e30f, l0 = 0.f, l1 = 0.f;
    float o[8][4];
    #pragma unroll
    for (int nt = 0; nt < 8; nt++)
        #pragma unroll
        for (int e = 0; e < 4; e++) o[nt][e] = 0.f;

    const uint32_t src1 = (uint32_t)((lane & ~3) | (tc >> 1));
    const uint32_t src2 = src1 | 2u;
    const bool     odd  = (tc & 1) != 0;

    for (int kt = 0; kt < 16; kt++) {
        CP_WAIT0();           // K(kt) landed (and all older groups)
        __syncthreads();      // K visible; every warp done with V(kt-1)

        const uint32_t kb = (kt & 1) ? sA : sBf;

        // issue V(kt) (its buffer is free: barrier above follows all PV(kt-1))
        {
            const float* Vt = Vg + (size_t)kt * 128 * HD;
            #pragma unroll
            for (int l = 0; l < 8; l++) {
                int r = flr + l * 16;
                cp16(sV + (r * AVSTR + flc) * 4, Vt + (size_t)r * HD + flc);
            }
        }
        CP_COMMIT();
        // issue K(kt+1) into the other K buffer
        if (kt < 15) {
            const uint32_t kn = (kt & 1) ? sBf : sA;
            const float* Kt = Kg + (size_t)(kt + 1) * 128 * HD;
            #pragma unroll
            for (int l = 0; l < 8; l++) {
                int r = flr + l * 16;
                cp16(kn + (r * AKSTR + flc) * 4, Kt + (size_t)r * HD + flc);
            }
            CP_COMMIT();
        }

        #pragma unroll
        for (int h = 0; h < 2; h++) {
            // ---- S = Q K^T for this 64-col half ----
            float sacc[8][4];
            #pragma unroll
            for (int nt = 0; nt < 8; nt++)
                #pragma unroll
                for (int e = 0; e < 4; e++) sacc[nt][e] = 0.f;

            const uint32_t kbh = kb + h * (64 * AKSTR * 4);
            #pragma unroll
            for (int ks = 0; ks < 8; ks++) {
                #pragma unroll
                for (int p = 0; p < 4; p++) {
                    uint32_t b0, b1, b2, b3;
                    ldm4(b0, b1, b2, b3, kbh + kOff[p] + ks * 32);
                    mma8(sacc[2 * p][0], sacc[2 * p][1], sacc[2 * p][2], sacc[2 * p][3],
                         qf[ks][0], qf[ks][1], qf[ks][2], qf[ks][3], b0, b1);
                    mma8(sacc[2 * p + 1][0], sacc[2 * p + 1][1], sacc[2 * p + 1][2], sacc[2 * p + 1][3],
                         qf[ks][0], qf[ks][1], qf[ks][2], qf[ks][3], b2, b3);
                }
            }

            // ---- register softmax (rows gr, gr+8) ----
            float mx0 = -1e30f, mx1 = -1e30f;
            #pragma unroll
            for (int nt = 0; nt < 8; nt++) {
                sacc[nt][0] *= 0.125f; sacc[nt][1] *= 0.125f;
                sacc[nt][2] *= 0.125f; sacc[nt][3] *= 0.125f;
                mx0 = fmaxf(mx0, fmaxf(sacc[nt][0], sacc[nt][1]));
                mx1 = fmaxf(mx1, fmaxf(sacc[nt][2], sacc[nt][3]));
            }
            mx0 = fmaxf(mx0, __shfl_xor_sync(0xFFFFFFFFu, mx0, 1));
            mx0 = fmaxf(mx0, __shfl_xor_sync(0xFFFFFFFFu, mx0, 2));
            mx1 = fmaxf(mx1, __shfl_xor_sync(0xFFFFFFFFu, mx1, 1));
            mx1 = fmaxf(mx1, __shfl_xor_sync(0xFFFFFFFFu, mx1, 2));
            const float mn0 = fmaxf(m0, mx0), mn1 = fmaxf(m1, mx1);
            const float c0 = __expf(m0 - mn0), c1 = __expf(m1 - mn1);
            float s0 = 0.f, s1 = 0.f;
            #pragma unroll
            for (int nt = 0; nt < 8; nt++) {
                sacc[nt][0] = __expf(sacc[nt][0] - mn0);
                sacc[nt][1] = __expf(sacc[nt][1] - mn0);
                sacc[nt][2] = __expf(sacc[nt][2] - mn1);
                sacc[nt][3] = __expf(sacc[nt][3] - mn1);
                s0 += sacc[nt][0] + sacc[nt][1];
                s1 += sacc[nt][2] + sacc[nt][3];
            }
            s0 += __shfl_xor_sync(0xFFFFFFFFu, s0, 1);
            s0 += __shfl_xor_sync(0xFFFFFFFFu, s0, 2);
            s1 += __shfl_xor_sync(0xFFFFFFFFu, s1, 1);
            s1 += __shfl_xor_sync(0xFFFFFFFFu, s1, 2);
            l0 = l0 * c0 + s0;  l1 = l1 * c1 + s1;
            m0 = mn0;           m1 = mn1;
            #pragma unroll
            for (int nt = 0; nt < 8; nt++) {
                o[nt][0] *= c0; o[nt][1] *= c0;
                o[nt][2] *= c1; o[nt][3] *= c1;
            }

            if (h == 0) {                 // V(kt) needed from here on
                if (kt < 15) { CP_WAIT1(); } else { CP_WAIT0(); }
                __syncthreads();          // V visible to all warps
            }

            // ---- o += P V for this half ----
            #pragma unroll
            for (int kp = 0; kp < 8; kp++) {
                const float p0 = tf32r(sacc[kp][0]);
                const float p1 = tf32r(sacc[kp][1]);
                const float p2 = tf32r(sacc[kp][2]);
                const float p3 = tf32r(sacc[kp][3]);
                const float t00 = __shfl_sync(0xFFFFFFFFu, p0, src1);
                const float t01 = __shfl_sync(0xFFFFFFFFu, p1, src1);
                const float t02 = __shfl_sync(0xFFFFFFFFu, p0, src2);
                const float t03 = __shfl_sync(0xFFFFFFFFu, p1, src2);
                const float t10 = __shfl_sync(0xFFFFFFFFu, p2, src1);
                const float t11 = __shfl_sync(0xFFFFFFFFu, p3, src1);
                const float t12 = __shfl_sync(0xFFFFFFFFu, p2, src2);
                const float t13 = __shfl_sync(0xFFFFFFFFu, p3, src2);
                const uint32_t a0 = __float_as_uint(odd ? t01 : t00);
                const uint32_t a2 = __float_as_uint(odd ? t03 : t02);
                const uint32_t a1 = __float_as_uint(odd ? t11 : t10);
                const uint32_t a3 = __float_as_uint(odd ? t13 : t12);

                const float* vb  = Vs + (size_t)(h * 64 + kp * 8 + tc) * AVSTR + gr;
                const float* vb4 = vb + 4 * AVSTR;
                #pragma unroll
                for (int nt = 0; nt < 8; nt++) {
                    const uint32_t b0 = __float_as_uint(vb[nt * 8]);
                    const uint32_t b1 = __float_as_uint(vb4[nt * 8]);
                    mma8(o[nt][0], o[nt][1], o[nt][2], o[nt][3],
                         a0, a1, a2, a3, b0, b1);
                }
            }
        }
    }

    // ---- normalize + store to g_O [B,S,H*D] ----
    const float i0 = 1.0f / l0;
    const float i1 = 1.0f / l1;
    const int b  = bh >> 4;
    const int hh = bh & 15;
    const int r0 = wid * 16 + gr;
    #pragma unroll
    for (int nt = 0; nt < 8; nt++) {
        const int d = nt * 8 + 2 * tc;
        {
            const int s_ = qt * 128 + r0;
            size_t idx = ((size_t)(b * Ss + s_)) * HIDn + hh * HD + d;
            *(float2*)(g_O + idx) = make_float2(o[nt][0] * i0, o[nt][1] * i0);
        }
        {
            const int s_ = qt * 128 + r0 + 8;
            size_t idx = ((size_t)(b * Ss + s_)) * HIDn + hh * HD + d;
            *(float2*)(g_O + idx) = make_float2(o[nt][2] * i1, o[nt][3] * i1);
        }
    }
}

// ============================================================================
// launch
// ============================================================================
extern "C" void kernel_launch(void* const* d_in, const int* in_sizes, int n_in,
                              void* d_out, int out_size)
{
    (void)in_sizes; (void)n_in; (void)out_size;
    const float* q  = (const float*)d_in[0];
    const float* k  = (const float*)d_in[1];
    const float* v  = (const float*)d_in[2];
    const float* wq = (const float*)d_in[3];
    const float* bq = (const float*)d_in[4];
    const float* wk = (const float*)d_in[5];
    const float* bk = (const float*)d_in[6];
    const float* wv = (const float*)d_in[7];
    const float* bv = (const float*)d_in[8];
    const float* wo = (const float*)d_in[9];
    const float* bo = (const float*)d_in[10];
    float* out = (float*)d_out;

    float *Qp, *Kp, *Vp, *Op, *WTp;
    cudaGetSymbolAddress((void**)&Qp,  g_Q);
    cudaGetSymbolAddress((void**)&Kp,  g_K);
    cudaGetSymbolAddress((void**)&Vp,  g_V);
    cudaGetSymbolAddress((void**)&Op,  g_O);
    cudaGetSymbolAddress((void**)&WTp, g_WT);

    cudaFuncSetAttribute(attn_kernel,
                         cudaFuncAttributeMaxDynamicSharedMemorySize, ATT_SMEM_BYTES);
    cudaFuncSetAttribute(gemm_tc<0>,
                         cudaFuncAttributeMaxDynamicSharedMemorySize, GEMM_SMEM);
    cudaFuncSetAttribute(gemm_tc<1>,
                         cudaFuncAttributeMaxDynamicSharedMemorySize, GEMM_SMEM);

    dim3 tgrid(32, 32), tblk(32, 8);
    dim3 ggrid(HIDn / 128, ROWS / 128);   // (8, 64)

    transpose1024<<<tgrid, tblk>>>(wq, WTp);
    gemm_tc<1><<<ggrid, 256, GEMM_SMEM>>>(q, WTp, bq, Qp);
    transpose1024<<<tgrid, tblk>>>(wk, WTp);
    gemm_tc<1><<<ggrid, 256, GEMM_SMEM>>>(k, WTp, bk, Kp);
    transpose1024<<<tgrid, tblk>>>(wv, WTp);
    gemm_tc<1><<<ggrid, 256, GEMM_SMEM>>>(v, WTp, bv, Vp);

    attn_kernel<<<dim3(Ss / 128, Bb * HEADS), 256, ATT_SMEM_BYTES>>>();

    transpose1024<<<tgrid, tblk>>>(wo, WTp);
    gemm_tc<0><<<ggrid, 256, GEMM_SMEM>>>(Op, WTp, bo, out);
}

// round 7
// speedup vs baseline: 1.6117x; 1.0106x over previous
#include <cuda_runtime.h>
#include <math.h>
#include <stdint.h>

// Problem constants
#define Bb   4
#define Ss   2048
#define HIDn 1024
#define HEADS 16
#define HD   64
#define ROWS (Bb*Ss)          // 8192

// ---------------- scratch (device globals: allocation-guard safe) ----------
__device__ float g_Q[Bb*HEADS*Ss*HD];   // [B,H,S,D] (tf32-rounded)
__device__ float g_K[Bb*HEADS*Ss*HD];
__device__ float g_V[Bb*HEADS*Ss*HD];
__device__ float g_O[Bb*Ss*HIDn];       // [B,S,H*D] row-major (tf32-rounded)
__device__ float g_WT[HIDn*HIDn];       // transposed + tf32-rounded weight
__device__ float g_A[ROWS*HIDn];        // tf32-rounded activation copy

// ============================================================================
// helpers
// ============================================================================
__device__ __forceinline__ uint32_t smem_u32(const void* p) {
    uint32_t a;
    asm("{ .reg .u64 t; cvta.to.shared.u64 t, %1; cvt.u32.u64 %0, t; }"
        : "=r"(a) : "l"(p));
    return a;
}
__device__ __forceinline__ uint32_t f2tf(float x) {
    uint32_t u;
    asm("cvt.rna.tf32.f32 %0, %1;" : "=r"(u) : "f"(x));
    return u;
}
__device__ __forceinline__ float tf32r(float x) { return __uint_as_float(f2tf(x)); }

__device__ __forceinline__ void mma8(float& d0, float& d1, float& d2, float& d3,
                                     uint32_t a0, uint32_t a1, uint32_t a2, uint32_t a3,
                                     uint32_t b0, uint32_t b1) {
    asm volatile(
        "mma.sync.aligned.m16n8k8.row.col.f32.tf32.tf32.f32 "
        "{%0,%1,%2,%3}, {%4,%5,%6,%7}, {%8,%9}, {%0,%1,%2,%3};"
        : "+f"(d0), "+f"(d1), "+f"(d2), "+f"(d3)
        : "r"(a0), "r"(a1), "r"(a2), "r"(a3), "r"(b0), "r"(b1));
}
__device__ __forceinline__ void ldm4(uint32_t& r0, uint32_t& r1, uint32_t& r2,
                                     uint32_t& r3, uint32_t addr) {
    asm volatile("ldmatrix.sync.aligned.m8n8.x4.shared.b16 {%0,%1,%2,%3}, [%4];"
                 : "=r"(r0), "=r"(r1), "=r"(r2), "=r"(r3) : "r"(addr));
}
__device__ __forceinline__ void cp16(uint32_t s, const void* g) {
    asm volatile("cp.async.cg.shared.global [%0], [%1], 16;" :: "r"(s), "l"(g));
}
#define CP_COMMIT() asm volatile("cp.async.commit_group;" ::: "memory")
#define CP_WAIT1()  asm volatile("cp.async.wait_group 1;"  ::: "memory")
#define CP_WAIT0()  asm volatile("cp.async.wait_group 0;"  ::: "memory")

// ============================================================================
// tf32 rounding prepass: out[i] = tf32(in[i]), vectorized
// ============================================================================
__global__ __launch_bounds__(256)
void round_tf32(const float4* __restrict__ in, float4* __restrict__ out)
{
    const int i = blockIdx.x * 256 + threadIdx.x;
    float4 v = in[i];
    v.x = tf32r(v.x); v.y = tf32r(v.y); v.z = tf32r(v.z); v.w = tf32r(v.w);
    out[i] = v;
}

// ============================================================================
// Weight transpose + tf32 rounding: WT[n][k] = tf32(W[k][n])
// ============================================================================
__global__ __launch_bounds__(256)
void transpose1024(const float* __restrict__ in, float* __restrict__ out)
{
    __shared__ float t[32][33];
    int x = blockIdx.x * 32 + threadIdx.x;
    int y0 = blockIdx.y * 32;
    #pragma unroll
    for (int l = 0; l < 32; l += 8)
        t[threadIdx.y + l][threadIdx.x] = in[(size_t)(y0 + threadIdx.y + l) * 1024 + x];
    __syncthreads();
    int xo = blockIdx.y * 32 + threadIdx.x;
    int yo = blockIdx.x * 32;
    #pragma unroll
    for (int l = 0; l < 32; l += 8)
        out[(size_t)(yo + threadIdx.y + l) * 1024 + xo] = tf32r(t[threadIdx.x][threadIdx.y + l]);
}

// ============================================================================
// tf32 mma.sync GEMM: C = A[M,1024] * W[1024,N] + bias.
// A pre-rounded to tf32; W pre-transposed+rounded (WT[N,1024], K-major).
// 128x128 tile/CTA, BK=32, 3-stage cp.async, ldmatrix frags, 2 CTAs/SM.
// MODE 0: C row-major [M,N] fp32.  MODE 1: scatter to [B,H,S,D], tf32-rounded.
// ============================================================================
#define GSTAGES 3
#define GASTR   36
#define GSTG    (128*GASTR)            // floats per stage per tensor
#define GSTGB   (GSTG*4)               // bytes per stage
#define GEMM_SMEM (2*GSTAGES*GSTGB)    // 110592 bytes

template<int MODE>
__global__ __launch_bounds__(256, 2)
void gemm_tc(const float* __restrict__ A, const float* __restrict__ WT,
             const float* __restrict__ bias, float* __restrict__ C)
{
    extern __shared__ float smf[];
    float* As = smf;                    // [3][128][36]
    float* Bs = smf + GSTAGES * GSTG;   // [3][128][36]
    const uint32_t sA = smem_u32(As);
    const uint32_t sB = smem_u32(Bs);

    const int tid  = threadIdx.x;
    const int wid  = tid >> 5;
    const int lane = tid & 31;
    const int gr   = lane >> 2;
    const int tc   = lane & 3;
    const int m8   = lane >> 3;
    const int e8   = lane & 7;
    const int wm   = wid & 1;          // 2 row groups of 64
    const int wn   = wid >> 1;         // 4 col groups of 32
    const int row0 = blockIdx.y * 128;
    const int col0 = blockIdx.x * 128;

    const float* Ag0 = A  + (size_t)row0 * 1024;
    const float* Bg0 = WT + (size_t)col0 * 1024;

    // ldmatrix lane offsets (bytes within a stage)
    uint32_t aOff[4], bOff[2];
    #pragma unroll
    for (int mt = 0; mt < 4; mt++)
        aOff[mt] = (uint32_t)(((wm * 64 + mt * 16 + e8 + ((m8 & 1) << 3)) * GASTR
                               + ((m8 >> 1) << 2)) << 2);
    #pragma unroll
    for (int p = 0; p < 2; p++)
        bOff[p] = (uint32_t)(((wn * 32 + p * 16 + ((m8 >> 1) << 3) + e8) * GASTR
                              + ((m8 & 1) << 2)) << 2);

    float acc[4][4][4];
    #pragma unroll
    for (int mt = 0; mt < 4; mt++)
        #pragma unroll
        for (int nt = 0; nt < 4; nt++)
            #pragma unroll
            for (int e = 0; e < 4; e++) acc[mt][nt][e] = 0.f;

    // stage loader: 128 rows x 32 floats each for A and B
    const int lr  = tid >> 3;          // 0..31
    const int lc4 = (tid & 7) << 2;    // 0..28
    #define LOAD_STAGE(st, chunk) do {                                         \
        const float* _Ag = Ag0 + (chunk) * 32;                                 \
        const float* _Bg = Bg0 + (chunk) * 32;                                 \
        uint32_t _aS = sA + (st) * GSTGB;                                      \
        uint32_t _bS = sB + (st) * GSTGB;                                      \
        _Pragma("unroll")                                                      \
        for (int l = 0; l < 4; l++) {                                          \
            int r = lr + l * 32;                                               \
            cp16(_aS + (r * GASTR + lc4) * 4, _Ag + (size_t)r * 1024 + lc4);   \
            cp16(_bS + (r * GASTR + lc4) * 4, _Bg + (size_t)r * 1024 + lc4);   \
        }                                                                      \
    } while (0)

    LOAD_STAGE(0, 0); CP_COMMIT();
    LOAD_STAGE(1, 1); CP_COMMIT();

    for (int i = 0; i < 32; i++) {
        const int s = i % 3;
        CP_WAIT1();
        __syncthreads();

        const int j = i + 2;
        if (j < 32) { LOAD_STAGE(j % 3, j); }
        CP_COMMIT();

        const uint32_t aBs = sA + s * GSTGB;
        const uint32_t bBs = sB + s * GSTGB;

        #pragma unroll
        for (int ks = 0; ks < 4; ks++) {
            uint32_t a[4][4], b[4][2];
            #pragma unroll
            for (int mt = 0; mt < 4; mt++)
                ldm4(a[mt][0], a[mt][1], a[mt][2], a[mt][3], aBs + aOff[mt] + ks * 32);
            #pragma unroll
            for (int p = 0; p < 2; p++) {
                uint32_t t0, t1, t2, t3;
                ldm4(t0, t1, t2, t3, bBs + bOff[p] + ks * 32);
                b[2 * p][0]     = t0; b[2 * p][1]     = t1;
                b[2 * p + 1][0] = t2; b[2 * p + 1][1] = t3;
            }
            #pragma unroll
            for (int mt = 0; mt < 4; mt++)
                #pragma unroll
                for (int nt = 0; nt < 4; nt++)
                    mma8(acc[mt][nt][0], acc[mt][nt][1], acc[mt][nt][2], acc[mt][nt][3],
                         a[mt][0], a[mt][1], a[mt][2], a[mt][3], b[nt][0], b[nt][1]);
        }
    }

    // ---- epilogue ----
    #pragma unroll
    for (int mt = 0; mt < 4; mt++) {
        const int r0 = row0 + wm * 64 + mt * 16 + gr;
        #pragma unroll
        for (int nt = 0; nt < 4; nt++) {
            const int c = col0 + wn * 32 + nt * 8 + 2 * tc;
            const float2 bi = *(const float2*)(bias + c);
            float v00 = acc[mt][nt][0] + bi.x, v01 = acc[mt][nt][1] + bi.y;
            float v10 = acc[mt][nt][2] + bi.x, v11 = acc[mt][nt][3] + bi.y;
            if (MODE == 1) {
                v00 = tf32r(v00); v01 = tf32r(v01);
                v10 = tf32r(v10); v11 = tf32r(v11);
            }
            if (MODE == 0) {
                *(float2*)(C + (size_t)r0 * 1024 + c)       = make_float2(v00, v01);
                *(float2*)(C + (size_t)(r0 + 8) * 1024 + c) = make_float2(v10, v11);
            } else {
                const int h = c >> 6, d = c & 63;
                {
                    const int b = r0 >> 11, s_ = r0 & 2047;
                    *(float2*)(C + ((((size_t)(b * HEADS + h)) * Ss + s_) * HD + d))
                        = make_float2(v00, v01);
                }
                {
                    const int r1 = r0 + 8;
                    const int b = r1 >> 11, s_ = r1 & 2047;
                    *(float2*)(C + ((((size_t)(b * HEADS + h)) * Ss + s_) * HD + d))
                        = make_float2(v10, v11);
                }
            }
        }
    }
}

// ============================================================================
// Flash attention, FA2-style + P staged through smem for ldmatrix PV frags.
// Block = (bh, 128-query tile), 256 threads / 8 warps, 2 CTAs/SM.
// smem: Ks 128x68 (single-buffer), Vs 128x72 (single-buffer, doubles as Q
// staging at startup), Ps 128x68 (per-warp 16-row regions; warp-private;
// 64 P columns per half + 4 pad).
// Per kt: QK0 -> softmax0 -> P0 st.v2 -> PV0 -> QK1 -> [prefetch K(kt+1)]
//         -> softmax1 -> P1 -> PV1 -> [prefetch V(kt+1)].
// ============================================================================
#define AKSTR 68
#define AVSTR 72
#define APSTR 68
#define ATT_SMEM_FLOATS (128*AKSTR + 128*AVSTR + 128*APSTR)
#define ATT_SMEM_BYTES  (ATT_SMEM_FLOATS * 4)   // 106496

__global__ __launch_bounds__(256, 2)
void attn_kernel()
{
    extern __shared__ float sm[];
    float* Ks = sm;                         // 128*68
    float* Vs = sm + 128 * AKSTR;           // 128*72 (Q staging at startup)
    float* Ps = sm + 128 * AKSTR + 128 * AVSTR;   // 128*68
    const uint32_t sK = smem_u32(Ks);
    const uint32_t sV = smem_u32(Vs);
    const uint32_t sP = smem_u32(Ps);

    const int bh   = blockIdx.y;
    const int qt   = blockIdx.x;
    const int tid  = threadIdx.x;
    const int wid  = tid >> 5;
    const int lane = tid & 31;
    const int gr   = lane >> 2;
    const int tc   = lane & 3;
    const int m8   = lane >> 3;
    const int e8   = lane & 7;

    const float* Qg = g_Q + (size_t)bh * Ss * HD + (size_t)qt * 128 * HD;
    const float* Kg = g_K + (size_t)bh * Ss * HD;
    const float* Vg = g_V + (size_t)bh * Ss * HD;

    const int flr = tid >> 4;               // 0..15
    const int flc = (tid & 15) << 2;        // 0..60

    // issue K(0)
    #pragma unroll
    for (int l = 0; l < 8; l++) {
        int r = flr + l * 16;
        cp16(sK + (r * AKSTR + flc) * 4, Kg + (size_t)r * HD + flc);
    }
    CP_COMMIT();

    // stage Q into Vs region (stride AKSTR), extract persistent fragments
    for (int f = tid; f < 2048; f += 256) {
        int r  = f >> 4;
        int c4 = (f & 15) << 2;
        float4 v = *(const float4*)(Qg + (size_t)r * HD + c4);
        float* q = Vs + r * AKSTR + c4;
        q[0] = v.x; q[1] = v.y; q[2] = v.z; q[3] = v.w;
    }
    __syncthreads();
    uint32_t qf[8][4];
    {
        const uint32_t qbase = sV + (uint32_t)(((wid * 16 + e8 + ((m8 & 1) << 3)) * AKSTR
                                                + ((m8 >> 1) << 2)) << 2);
        #pragma unroll
        for (int ks = 0; ks < 8; ks++)
            ldm4(qf[ks][0], qf[ks][1], qf[ks][2], qf[ks][3], qbase + ks * 32);
    }
    __syncthreads();   // all warps done reading Q before V(0) overwrites

    // issue V(0)
    #pragma unroll
    for (int l = 0; l < 8; l++) {
        int r = flr + l * 16;
        cp16(sV + (r * AVSTR + flc) * 4, Vg + (size_t)r * HD + flc);
    }
    CP_COMMIT();

    // fragment lane offsets
    uint32_t kOff[4];
    #pragma unroll
    for (int p = 0; p < 4; p++)
        kOff[p] = (uint32_t)(((p * 16 + ((m8 >> 1) << 3) + e8) * AKSTR
                              + ((m8 & 1) << 2)) << 2);
    const uint32_t pLdBase = sP + (uint32_t)(((wid * 16 + e8 + ((m8 & 1) << 3)) * APSTR
                                              + ((m8 >> 1) << 2)) << 2);
    float* pSt0 = Ps + (wid * 16 + gr) * APSTR + 2 * tc;       // row gr
    float* pSt1 = pSt0 + 8 * APSTR;                             // row gr+8

    float m0 = -1e30f, m1 = -1e30f, l0 = 0.f, l1 = 0.f;
    float o[8][4];
    #pragma unroll
    for (int nt = 0; nt < 8; nt++)
        #pragma unroll
        for (int e = 0; e < 4; e++) o[nt][e] = 0.f;

    for (int kt = 0; kt < 16; kt++) {
        CP_WAIT1();           // K(kt) landed (V(kt) may be in flight)
        __syncthreads();      // K visible to all warps

        #pragma unroll
        for (int h = 0; h < 2; h++) {
            // ---- S = Q K^T for this 64-col half ----
            float sacc[8][4];
            #pragma unroll
            for (int nt = 0; nt < 8; nt++)
                #pragma unroll
                for (int e = 0; e < 4; e++) sacc[nt][e] = 0.f;

            const uint32_t kbh = sK + h * (64 * AKSTR * 4);
            #pragma unroll
            for (int ks = 0; ks < 8; ks++) {
                #pragma unroll
                for (int p = 0; p < 4; p++) {
                    uint32_t b0, b1, b2, b3;
                    ldm4(b0, b1, b2, b3, kbh + kOff[p] + ks * 32);
                    mma8(sacc[2 * p][0], sacc[2 * p][1], sacc[2 * p][2], sacc[2 * p][3],
                         qf[ks][0], qf[ks][1], qf[ks][2], qf[ks][3], b0, b1);
                    mma8(sacc[2 * p + 1][0], sacc[2 * p + 1][1], sacc[2 * p + 1][2], sacc[2 * p + 1][3],
                         qf[ks][0], qf[ks][1], qf[ks][2], qf[ks][3], b2, b3);
                }
            }

            if (h == 1) {
                // all warps are past their K reads for this kt
                __syncthreads();
                if (kt < 15) {       // prefetch K(kt+1); overlaps softmax1+PV1
                    const float* Kt = Kg + (size_t)(kt + 1) * 128 * HD;
                    #pragma unroll
                    for (int l = 0; l < 8; l++) {
                        int r = flr + l * 16;
                        cp16(sK + (r * AKSTR + flc) * 4, Kt + (size_t)r * HD + flc);
                    }
                }
                CP_COMMIT();
            }

            // ---- register softmax (rows gr, gr+8) ----
            float mx0 = -1e30f, mx1 = -1e30f;
            #pragma unroll
            for (int nt = 0; nt < 8; nt++) {
                sacc[nt][0] *= 0.125f; sacc[nt][1] *= 0.125f;
                sacc[nt][2] *= 0.125f; sacc[nt][3] *= 0.125f;
                mx0 = fmaxf(mx0, fmaxf(sacc[nt][0], sacc[nt][1]));
                mx1 = fmaxf(mx1, fmaxf(sacc[nt][2], sacc[nt][3]));
            }
            mx0 = fmaxf(mx0, __shfl_xor_sync(0xFFFFFFFFu, mx0, 1));
            mx0 = fmaxf(mx0, __shfl_xor_sync(0xFFFFFFFFu, mx0, 2));
            mx1 = fmaxf(mx1, __shfl_xor_sync(0xFFFFFFFFu, mx1, 1));
            mx1 = fmaxf(mx1, __shfl_xor_sync(0xFFFFFFFFu, mx1, 2));
            const float mn0 = fmaxf(m0, mx0), mn1 = fmaxf(m1, mx1);
            const float c0 = __expf(m0 - mn0), c1 = __expf(m1 - mn1);
            float s0 = 0.f, s1 = 0.f;
            #pragma unroll
            for (int nt = 0; nt < 8; nt++) {
                sacc[nt][0] = __expf(sacc[nt][0] - mn0);
                sacc[nt][1] = __expf(sacc[nt][1] - mn0);
                sacc[nt][2] = __expf(sacc[nt][2] - mn1);
                sacc[nt][3] = __expf(sacc[nt][3] - mn1);
                s0 += sacc[nt][0] + sacc[nt][1];
                s1 += sacc[nt][2] + sacc[nt][3];
            }
            s0 += __shfl_xor_sync(0xFFFFFFFFu, s0, 1);
            s0 += __shfl_xor_sync(0xFFFFFFFFu, s0, 2);
            s1 += __shfl_xor_sync(0xFFFFFFFFu, s1, 1);
            s1 += __shfl_xor_sync(0xFFFFFFFFu, s1, 2);
            l0 = l0 * c0 + s0;  l1 = l1 * c1 + s1;
            m0 = mn0;           m1 = mn1;
            #pragma unroll
            for (int nt = 0; nt < 8; nt++) {
                o[nt][0] *= c0; o[nt][1] *= c0;
                o[nt][2] *= c1; o[nt][3] *= c1;
            }

            // ---- stage P (tf32-rounded) into warp-private smem ----
            #pragma unroll
            for (int nt = 0; nt < 8; nt++) {
                *(float2*)(pSt0 + nt * 8) = make_float2(tf32r(sacc[nt][0]), tf32r(sacc[nt][1]));
                *(float2*)(pSt1 + nt * 8) = make_float2(tf32r(sacc[nt][2]), tf32r(sacc[nt][3]));
            }
            __syncwarp();

            if (h == 0) {                 // V(kt) needed from here on
                CP_WAIT1();               // V(kt) landed (K(kt+1) not yet committed)
                __syncthreads();          // V visible to all warps
            }

            // ---- o += P V for this half (A-frags from Ps via ldmatrix) ----
            #pragma unroll
            for (int kp = 0; kp < 8; kp++) {
                uint32_t a0, a1, a2, a3;
                ldm4(a0, a1, a2, a3, pLdBase + kp * 32);
                const float* vb  = Vs + (size_t)(h * 64 + kp * 8 + tc) * AVSTR + gr;
                const float* vb4 = vb + 4 * AVSTR;
                #pragma unroll
                for (int nt = 0; nt < 8; nt++) {
                    const uint32_t b0 = __float_as_uint(vb[nt * 8]);
                    const uint32_t b1 = __float_as_uint(vb4[nt * 8]);
                    mma8(o[nt][0], o[nt][1], o[nt][2], o[nt][3],
                         a0, a1, a2, a3, b0, b1);
                }
            }
        }

        __syncthreads();      // all warps done reading V(kt)
        if (kt < 15) {        // prefetch V(kt+1); overlaps next QK0+softmax0
            const float* Vt = Vg + (size_t)(kt + 1) * 128 * HD;
            #pragma unroll
            for (int l = 0; l < 8; l++) {
                int r = flr + l * 16;
                cp16(sV + (r * AVSTR + flc) * 4, Vt + (size_t)r * HD + flc);
            }
        }
        CP_COMMIT();
    }

    // ---- normalize + store to g_O [B,S,H*D] (tf32-rounded for final GEMM) --
    const float i0 = 1.0f / l0;
    const float i1 = 1.0f / l1;
    const int b  = bh >> 4;
    const int hh = bh & 15;
    const int r0 = wid * 16 + gr;
    #pragma unroll
    for (int nt = 0; nt < 8; nt++) {
        const int d = nt * 8 + 2 * tc;
        {
            const int s_ = qt * 128 + r0;
            size_t idx = ((size_t)(b * Ss + s_)) * HIDn + hh * HD + d;
            *(float2*)(g_O + idx) = make_float2(tf32r(o[nt][0] * i0), tf32r(o[nt][1] * i0));
        }
        {
            const int s_ = qt * 128 + r0 + 8;
            size_t idx = ((size_t)(b * Ss + s_)) * HIDn + hh * HD + d;
            *(float2*)(g_O + idx) = make_float2(tf32r(o[nt][2] * i1), tf32r(o[nt][3] * i1));
        }
    }
}

// ============================================================================
// launch
// ============================================================================
extern "C" void kernel_launch(void* const* d_in, const int* in_sizes, int n_in,
                              void* d_out, int out_size)
{
    (void)in_sizes; (void)n_in; (void)out_size;
    const float* q  = (const float*)d_in[0];
    const float* k  = (const float*)d_in[1];
    const float* v  = (const float*)d_in[2];
    const float* wq = (const float*)d_in[3];
    const float* bq = (const float*)d_in[4];
    const float* wk = (const float*)d_in[5];
    const float* bk = (const float*)d_in[6];
    const float* wv = (const float*)d_in[7];
    const float* bv = (const float*)d_in[8];
    const float* wo = (const float*)d_in[9];
    const float* bo = (const float*)d_in[10];
    float* out = (float*)d_out;

    float *Qp, *Kp, *Vp, *Op, *WTp, *Ap;
    cudaGetSymbolAddress((void**)&Qp,  g_Q);
    cudaGetSymbolAddress((void**)&Kp,  g_K);
    cudaGetSymbolAddress((void**)&Vp,  g_V);
    cudaGetSymbolAddress((void**)&Op,  g_O);
    cudaGetSymbolAddress((void**)&WTp, g_WT);
    cudaGetSymbolAddress((void**)&Ap,  g_A);

    cudaFuncSetAttribute(attn_kernel,
                         cudaFuncAttributeMaxDynamicSharedMemorySize, ATT_SMEM_BYTES);
    cudaFuncSetAttribute(gemm_tc<0>,
                         cudaFuncAttributeMaxDynamicSharedMemorySize, GEMM_SMEM);
    cudaFuncSetAttribute(gemm_tc<1>,
                         cudaFuncAttributeMaxDynamicSharedMemorySize, GEMM_SMEM);

    dim3 tgrid(32, 32), tblk(32, 8);
    dim3 ggrid(HIDn / 128, ROWS / 128);   // (8, 64)
    const int rblocks = ROWS * HIDn / 4 / 256;   // 8192

    transpose1024<<<tgrid, tblk>>>(wq, WTp);
    round_tf32<<<rblocks, 256>>>((const float4*)q, (float4*)Ap);
    gemm_tc<1><<<ggrid, 256, GEMM_SMEM>>>(Ap, WTp, bq, Qp);

    transpose1024<<<tgrid, tblk>>>(wk, WTp);
    round_tf32<<<rblocks, 256>>>((const float4*)k, (float4*)Ap);
    gemm_tc<1><<<ggrid, 256, GEMM_SMEM>>>(Ap, WTp, bk, Kp);

    transpose1024<<<tgrid, tblk>>>(wv, WTp);
    round_tf32<<<rblocks, 256>>>((const float4*)v, (float4*)Ap);
    gemm_tc<1><<<ggrid, 256, GEMM_SMEM>>>(Ap, WTp, bv, Vp);

    attn_kernel<<<dim3(Ss / 128, Bb * HEADS), 256, ATT_SMEM_BYTES>>>();

    transpose1024<<<tgrid, tblk>>>(wo, WTp);
    gemm_tc<0><<<ggrid, 256, GEMM_SMEM>>>(Op, WTp, bo, out);
}

// round 8
// speedup vs baseline: 2.7293x; 1.6934x over previous
#include <cuda_runtime.h>
#include <cuda_fp16.h>
#include <math.h>
#include <stdint.h>

// Problem constants
#define Bb   4
#define Ss   2048
#define HIDn 1024
#define HEADS 16
#define HD   64
#define ROWS (Bb*Ss)          // 8192

// ---------------- scratch (device globals: allocation-guard safe) ----------
__device__ __half g_Q[Bb*HEADS*Ss*HD];   // [B,H,S,D] fp16 (rna-rounded)
__device__ __half g_K[Bb*HEADS*Ss*HD];
__device__ __half g_V[Bb*HEADS*Ss*HD];
__device__ __half g_O[Bb*Ss*HIDn];       // [B,S,H*D] fp16
__device__ __half g_WT[HIDn*HIDn];       // transposed + rounded weight, [N][K]
__device__ __half g_A[ROWS*HIDn];        // rounded activation copy

// ============================================================================
// helpers
// ============================================================================
__device__ __forceinline__ uint32_t smem_u32(const void* p) {
    uint32_t a;
    asm("{ .reg .u64 t; cvta.to.shared.u64 t, %1; cvt.u32.u64 %0, t; }"
        : "=r"(a) : "l"(p));
    return a;
}
__device__ __forceinline__ void mma16(float& d0, float& d1, float& d2, float& d3,
                                      uint32_t a0, uint32_t a1, uint32_t a2, uint32_t a3,
                                      uint32_t b0, uint32_t b1) {
    asm volatile(
        "mma.sync.aligned.m16n8k16.row.col.f32.f16.f16.f32 "
        "{%0,%1,%2,%3}, {%4,%5,%6,%7}, {%8,%9}, {%0,%1,%2,%3};"
        : "+f"(d0), "+f"(d1), "+f"(d2), "+f"(d3)
        : "r"(a0), "r"(a1), "r"(a2), "r"(a3), "r"(b0), "r"(b1));
}
__device__ __forceinline__ void ldm4(uint32_t& r0, uint32_t& r1, uint32_t& r2,
                                     uint32_t& r3, uint32_t addr) {
    asm volatile("ldmatrix.sync.aligned.m8n8.x4.shared.b16 {%0,%1,%2,%3}, [%4];"
                 : "=r"(r0), "=r"(r1), "=r"(r2), "=r"(r3) : "r"(addr));
}
__device__ __forceinline__ void ldm4t(uint32_t& r0, uint32_t& r1, uint32_t& r2,
                                      uint32_t& r3, uint32_t addr) {
    asm volatile("ldmatrix.sync.aligned.m8n8.x4.trans.shared.b16 {%0,%1,%2,%3}, [%4];"
                 : "=r"(r0), "=r"(r1), "=r"(r2), "=r"(r3) : "r"(addr));
}
__device__ __forceinline__ void cp16(uint32_t s, const void* g) {
    asm volatile("cp.async.cg.shared.global [%0], [%1], 16;" :: "r"(s), "l"(g));
}
#define CP_COMMIT() asm volatile("cp.async.commit_group;" ::: "memory")
#define CP_WAIT1()  asm volatile("cp.async.wait_group 1;"  ::: "memory")
#define CP_WAIT0()  asm volatile("cp.async.wait_group 0;"  ::: "memory")

// ============================================================================
// fp16 rounding prepass: 4 floats -> 4 halves per thread
// ============================================================================
__global__ __launch_bounds__(256)
void round_fp16(const float4* __restrict__ in, __half2* __restrict__ out)
{
    const int i = blockIdx.x * 256 + threadIdx.x;
    float4 v = in[i];
    out[2 * i]     = __floats2half2_rn(v.x, v.y);
    out[2 * i + 1] = __floats2half2_rn(v.z, v.w);
}

// ============================================================================
// Weight transpose + fp16 rounding: WT[n][k] = h(W[k][n])
// ============================================================================
__global__ __launch_bounds__(256)
void transpose1024(const float* __restrict__ in, __half* __restrict__ out)
{
    __shared__ float t[32][33];
    int x = blockIdx.x * 32 + threadIdx.x;
    int y0 = blockIdx.y * 32;
    #pragma unroll
    for (int l = 0; l < 32; l += 8)
        t[threadIdx.y + l][threadIdx.x] = in[(size_t)(y0 + threadIdx.y + l) * 1024 + x];
    __syncthreads();
    int xo = blockIdx.y * 32 + threadIdx.x;
    int yo = blockIdx.x * 32;
    #pragma unroll
    for (int l = 0; l < 32; l += 8)
        out[(size_t)(yo + threadIdx.y + l) * 1024 + xo] =
            __float2half_rn(t[threadIdx.x][threadIdx.y + l]);
}

// ============================================================================
// fp16 mma.sync GEMM: C = A[M,1024] * W[1024,N] + bias.
// A pre-rounded fp16; WT[N,1024] fp16 K-major. 128x128 tile/CTA, BK=64,
// 3-stage cp.async, ldmatrix b16 frags, 2 CTAs/SM.
// smem row: 64 halves + 8 pad = 144B (conflict-free ldmatrix phases).
// MODE 0: C row-major [M,N] fp32.  MODE 1: scatter to [B,H,S,D] fp16.
// ============================================================================
#define GSTR_B   144                   // bytes per smem row
#define GSTG_B   (128*GSTR_B)          // 18432 bytes per stage per tensor
#define GEMM_SMEM (2*3*GSTG_B)         // 110592 bytes

template<int MODE>
__global__ __launch_bounds__(256, 2)
void gemm_tc(const __half* __restrict__ A, const __half* __restrict__ WT,
             const float* __restrict__ bias, void* __restrict__ Cv)
{
    extern __shared__ __align__(16) char smc[];
    const uint32_t sA = smem_u32(smc);                 // A stages [3]
    const uint32_t sB = sA + 3 * GSTG_B;               // B stages [3]

    const int tid  = threadIdx.x;
    const int wid  = tid >> 5;
    const int lane = tid & 31;
    const int gr   = lane >> 2;
    const int tc   = lane & 3;
    const int m8   = lane >> 3;
    const int e8   = lane & 7;
    const int wm   = wid & 1;
    const int wn   = wid >> 1;
    const int row0 = blockIdx.y * 128;
    const int col0 = blockIdx.x * 128;

    const __half* Ag0 = A  + (size_t)row0 * 1024;
    const __half* Bg0 = WT + (size_t)col0 * 1024;

    // ldmatrix lane offsets (bytes within a stage)
    const int lrow = e8 + ((m8 & 1) << 3);             // 0..15
    const int lcolB = (m8 >> 1) << 4;                  // 0 or 16 or 32 or 48? -> (m8>>1)*16
    uint32_t aOff[4], bOff[2];
    #pragma unroll
    for (int mt = 0; mt < 4; mt++)
        aOff[mt] = (uint32_t)((wm * 64 + mt * 16 + lrow) * GSTR_B + lcolB);
    #pragma unroll
    for (int p = 0; p < 2; p++)
        bOff[p] = (uint32_t)((wn * 32 + p * 16 + lrow) * GSTR_B + lcolB);

    float acc[4][4][4];
    #pragma unroll
    for (int mt = 0; mt < 4; mt++)
        #pragma unroll
        for (int nt = 0; nt < 4; nt++)
            #pragma unroll
            for (int e = 0; e < 4; e++) acc[mt][nt][e] = 0.f;

    // stage loader: 128 rows x 64 halves (128B) per tensor -> 4 cp16/thread ea
    const int lr  = tid >> 3;          // 0..31
    const int lc  = tid & 7;           // 16B column
    #define LOAD_STAGE(st, chunk) do {                                          \
        const __half* _Ag = Ag0 + (chunk) * 64;                                 \
        const __half* _Bg = Bg0 + (chunk) * 64;                                 \
        uint32_t _aS = sA + (st) * GSTG_B;                                      \
        uint32_t _bS = sB + (st) * GSTG_B;                                      \
        _Pragma("unroll")                                                       \
        for (int l = 0; l < 4; l++) {                                           \
            int r = lr + l * 32;                                                \
            cp16(_aS + r * GSTR_B + lc * 16, _Ag + (size_t)r * 1024 + lc * 8);  \
            cp16(_bS + r * GSTR_B + lc * 16, _Bg + (size_t)r * 1024 + lc * 8);  \
        }                                                                       \
    } while (0)

    LOAD_STAGE(0, 0); CP_COMMIT();
    LOAD_STAGE(1, 1); CP_COMMIT();

    for (int i = 0; i < 16; i++) {
        const int s = i % 3;
        CP_WAIT1();
        __syncthreads();

        const int j = i + 2;
        if (j < 16) { LOAD_STAGE(j % 3, j); }
        CP_COMMIT();

        const uint32_t aBs = sA + s * GSTG_B;
        const uint32_t bBs = sB + s * GSTG_B;

        #pragma unroll
        for (int ks = 0; ks < 4; ks++) {        // 16 k per step, 32B col step
            uint32_t a[4][4], b[4][2];
            #pragma unroll
            for (int mt = 0; mt < 4; mt++)
                ldm4(a[mt][0], a[mt][1], a[mt][2], a[mt][3],
                     aBs + aOff[mt] + ks * 32);
            #pragma unroll
            for (int p = 0; p < 2; p++) {
                uint32_t t0, t1, t2, t3;
                ldm4(t0, t1, t2, t3, bBs + bOff[p] + ks * 32);
                b[2 * p][0]     = t0; b[2 * p][1]     = t2;   // {klo,khi} n0-7
                b[2 * p + 1][0] = t1; b[2 * p + 1][1] = t3;   // n8-15
            }
            #pragma unroll
            for (int mt = 0; mt < 4; mt++)
                #pragma unroll
                for (int nt = 0; nt < 4; nt++)
                    mma16(acc[mt][nt][0], acc[mt][nt][1], acc[mt][nt][2], acc[mt][nt][3],
                          a[mt][0], a[mt][1], a[mt][2], a[mt][3], b[nt][0], b[nt][1]);
        }
    }

    // ---- epilogue ----
    #pragma unroll
    for (int mt = 0; mt < 4; mt++) {
        const int r0 = row0 + wm * 64 + mt * 16 + gr;
        #pragma unroll
        for (int nt = 0; nt < 4; nt++) {
            const int c = col0 + wn * 32 + nt * 8 + 2 * tc;
            const float2 bi = *(const float2*)(bias + c);
            float v00 = acc[mt][nt][0] + bi.x, v01 = acc[mt][nt][1] + bi.y;
            float v10 = acc[mt][nt][2] + bi.x, v11 = acc[mt][nt][3] + bi.y;
            if (MODE == 0) {
                float* C = (float*)Cv;
                *(float2*)(C + (size_t)r0 * 1024 + c)       = make_float2(v00, v01);
                *(float2*)(C + (size_t)(r0 + 8) * 1024 + c) = make_float2(v10, v11);
            } else {
                __half* C = (__half*)Cv;
                const int h = c >> 6, d = c & 63;
                {
                    const int b = r0 >> 11, s_ = r0 & 2047;
                    *(__half2*)(C + ((((size_t)(b * HEADS + h)) * Ss + s_) * HD + d))
                        = __floats2half2_rn(v00, v01);
                }
                {
                    const int r1 = r0 + 8;
                    const int b = r1 >> 11, s_ = r1 & 2047;
                    *(__half2*)(C + ((((size_t)(b * HEADS + h)) * Ss + s_) * HD + d))
                        = __floats2half2_rn(v10, v11);
                }
            }
        }
    }
}

// ============================================================================
// Flash attention, fp16 mma.sync, FA2-style, fully double-buffered K and V.
// Block = (bh, 128-query tile), 256 threads / 8 warps, 2 CTAs/SM.
// smem: K[2] 128x(64+8)h, V[2] same, P 128x(64+8)h (per-warp 16-row regions;
// Q staged through the P region at startup). 1 __syncthreads per kt.
// ============================================================================
#define ASTR_B   144                        // bytes per smem row (72 halves)
#define ATILE_B  (128*ASTR_B)               // 18432
#define KB_OFF   0
#define VB_OFF   (2*ATILE_B)
#define PS_OFF   (4*ATILE_B)
#define ATT_SMEM_BYTES (5*ATILE_B)          // 92160

__global__ __launch_bounds__(256, 2)
void attn_kernel()
{
    extern __shared__ __align__(16) char smc[];
    const uint32_t sBase = smem_u32(smc);
    const uint32_t sKB = sBase + KB_OFF;
    const uint32_t sVB = sBase + VB_OFF;
    const uint32_t sPS = sBase + PS_OFF;

    const int bh   = blockIdx.y;
    const int qt   = blockIdx.x;
    const int tid  = threadIdx.x;
    const int wid  = tid >> 5;
    const int lane = tid & 31;
    const int gr   = lane >> 2;
    const int tc   = lane & 3;
    const int m8   = lane >> 3;
    const int e8   = lane & 7;

    const __half* Qg = g_Q + (size_t)bh * Ss * HD + (size_t)qt * 128 * HD;
    const __half* Kg = g_K + (size_t)bh * Ss * HD;
    const __half* Vg = g_V + (size_t)bh * Ss * HD;

    const int lr = tid >> 3;               // 0..31
    const int lc = tid & 7;                // 16B col

    // loader for one (K,V) tile pair into buffers (kt&1)
    #define LOAD_KV(kt) do {                                                    \
        const __half* _Kt = Kg + (size_t)(kt) * 128 * HD;                       \
        const __half* _Vt = Vg + (size_t)(kt) * 128 * HD;                       \
        uint32_t _kS = sKB + ((kt) & 1) * ATILE_B;                              \
        uint32_t _vS = sVB + ((kt) & 1) * ATILE_B;                              \
        _Pragma("unroll")                                                       \
        for (int l = 0; l < 4; l++) {                                           \
            int r = lr + l * 32;                                                \
            cp16(_kS + r * ASTR_B + lc * 16, _Kt + (size_t)r * HD + lc * 8);    \
            cp16(_vS + r * ASTR_B + lc * 16, _Vt + (size_t)r * HD + lc * 8);    \
        }                                                                       \
    } while (0)

    // prologue: issue K0+V0
    LOAD_KV(0); CP_COMMIT();

    // stage Q into the P region (stride 144B), extract persistent fragments
    {
        __half* Pq = (__half*)(smc + PS_OFF);
        #pragma unroll
        for (int l = 0; l < 4; l++) {
            int r = lr + l * 32;
            *(uint4*)((char*)Pq + r * ASTR_B + lc * 16) =
                *(const uint4*)(Qg + (size_t)r * HD + lc * 8);
        }
    }
    __syncthreads();
    const int lrow = e8 + ((m8 & 1) << 3);
    const int lcolB = (m8 >> 1) << 4;
    uint32_t qf[4][4];
    {
        const uint32_t qbase = sPS + (uint32_t)((wid * 16 + lrow) * ASTR_B + lcolB);
        #pragma unroll
        for (int ks = 0; ks < 4; ks++)
            ldm4(qf[ks][0], qf[ks][1], qf[ks][2], qf[ks][3], qbase + ks * 32);
    }

    // fragment lane offsets
    uint32_t kOff[4];
    #pragma unroll
    for (int p = 0; p < 4; p++)
        kOff[p] = (uint32_t)((p * 16 + lrow) * ASTR_B + lcolB);
    const uint32_t vOff = (uint32_t)(lrow * ASTR_B + lcolB);
    const uint32_t pLdBase = sPS + (uint32_t)(wid * 16 * ASTR_B + lrow * ASTR_B + lcolB);
    __half* pSt0 = (__half*)(smc + PS_OFF) + (wid * 16 + gr) * 72 + 2 * tc;
    __half* pSt1 = pSt0 + 8 * 72;

    float m0 = -1e30f, m1 = -1e30f, l0 = 0.f, l1 = 0.f;
    float o[8][4];
    #pragma unroll
    for (int nt = 0; nt < 8; nt++)
        #pragma unroll
        for (int e = 0; e < 4; e++) o[nt][e] = 0.f;

    for (int kt = 0; kt < 16; kt++) {
        CP_WAIT0();           // K(kt),V(kt) landed
        __syncthreads();      // visible; prev-iter buffer reads complete

        if (kt < 15) { LOAD_KV(kt + 1); CP_COMMIT(); }

        const uint32_t kb = sKB + (kt & 1) * ATILE_B;
        const uint32_t vb = sVB + (kt & 1) * ATILE_B;

        #pragma unroll
        for (int h = 0; h < 2; h++) {
            // ---- S = Q K^T for 64 keys ----
            float sacc[8][4];
            #pragma unroll
            for (int nt = 0; nt < 8; nt++)
                #pragma unroll
                for (int e = 0; e < 4; e++) sacc[nt][e] = 0.f;

            const uint32_t kbh = kb + h * (64 * ASTR_B);
            #pragma unroll
            for (int ks = 0; ks < 4; ks++) {
                #pragma unroll
                for (int p = 0; p < 4; p++) {
                    uint32_t t0, t1, t2, t3;
                    ldm4(t0, t1, t2, t3, kbh + kOff[p] + ks * 32);
                    mma16(sacc[2 * p][0], sacc[2 * p][1], sacc[2 * p][2], sacc[2 * p][3],
                          qf[ks][0], qf[ks][1], qf[ks][2], qf[ks][3], t0, t2);
                    mma16(sacc[2 * p + 1][0], sacc[2 * p + 1][1],
                          sacc[2 * p + 1][2], sacc[2 * p + 1][3],
                          qf[ks][0], qf[ks][1], qf[ks][2], qf[ks][3], t1, t3);
                }
            }

            // ---- register softmax (rows gr, gr+8) ----
            float mx0 = -1e30f, mx1 = -1e30f;
            #pragma unroll
            for (int nt = 0; nt < 8; nt++) {
                sacc[nt][0] *= 0.125f; sacc[nt][1] *= 0.125f;
                sacc[nt][2] *= 0.125f; sacc[nt][3] *= 0.125f;
                mx0 = fmaxf(mx0, fmaxf(sacc[nt][0], sacc[nt][1]));
                mx1 = fmaxf(mx1, fmaxf(sacc[nt][2], sacc[nt][3]));
            }
            mx0 = fmaxf(mx0, __shfl_xor_sync(0xFFFFFFFFu, mx0, 1));
            mx0 = fmaxf(mx0, __shfl_xor_sync(0xFFFFFFFFu, mx0, 2));
            mx1 = fmaxf(mx1, __shfl_xor_sync(0xFFFFFFFFu, mx1, 1));
            mx1 = fmaxf(mx1, __shfl_xor_sync(0xFFFFFFFFu, mx1, 2));
            const float mn0 = fmaxf(m0, mx0), mn1 = fmaxf(m1, mx1);
            const float c0 = __expf(m0 - mn0), c1 = __expf(m1 - mn1);
            float s0 = 0.f, s1 = 0.f;
            #pragma unroll
            for (int nt = 0; nt < 8; nt++) {
                sacc[nt][0] = __expf(sacc[nt][0] - mn0);
                sacc[nt][1] = __expf(sacc[nt][1] - mn0);
                sacc[nt][2] = __expf(sacc[nt][2] - mn1);
                sacc[nt][3] = __expf(sacc[nt][3] - mn1);
                s0 += sacc[nt][0] + sacc[nt][1];
                s1 += sacc[nt][2] + sacc[nt][3];
            }
            s0 += __shfl_xor_sync(0xFFFFFFFFu, s0, 1);
            s0 += __shfl_xor_sync(0xFFFFFFFFu, s0, 2);
            s1 += __shfl_xor_sync(0xFFFFFFFFu, s1, 1);
            s1 += __shfl_xor_sync(0xFFFFFFFFu, s1, 2);
            l0 = l0 * c0 + s0;  l1 = l1 * c1 + s1;
            m0 = mn0;           m1 = mn1;
            #pragma unroll
            for (int nt = 0; nt < 8; nt++) {
                o[nt][0] *= c0; o[nt][1] *= c0;
                o[nt][2] *= c1; o[nt][3] *= c1;
            }

            // ---- stage P as fp16 into warp-private smem ----
            #pragma unroll
            for (int nt = 0; nt < 8; nt++) {
                *(__half2*)(pSt0 + nt * 8) = __floats2half2_rn(sacc[nt][0], sacc[nt][1]);
                *(__half2*)(pSt1 + nt * 8) = __floats2half2_rn(sacc[nt][2], sacc[nt][3]);
            }
            __syncwarp();

            // ---- o += P V for this half (V B-frags via ldmatrix.trans) ----
            const uint32_t vbh = vb + h * (64 * ASTR_B);
            #pragma unroll
            for (int kp = 0; kp < 4; kp++) {          // 16 keys per step
                uint32_t a0, a1, a2, a3;
                ldm4(a0, a1, a2, a3, pLdBase + kp * 32);
                #pragma unroll
                for (int np = 0; np < 4; np++) {      // 16 d-cols per step
                    uint32_t t0, t1, t2, t3;
                    ldm4t(t0, t1, t2, t3, vbh + vOff + kp * (16 * ASTR_B) + np * 32);
                    mma16(o[2 * np][0], o[2 * np][1], o[2 * np][2], o[2 * np][3],
                          a0, a1, a2, a3, t0, t1);
                    mma16(o[2 * np + 1][0], o[2 * np + 1][1],
                          o[2 * np + 1][2], o[2 * np + 1][3],
                          a0, a1, a2, a3, t2, t3);
                }
            }
        }
    }

    // ---- normalize + store to g_O [B,S,H*D] fp16 ----
    const float i0 = 1.0f / l0;
    const float i1 = 1.0f / l1;
    const int b  = bh >> 4;
    const int hh = bh & 15;
    const int r0 = wid * 16 + gr;
    #pragma unroll
    for (int nt = 0; nt < 8; nt++) {
        const int d = nt * 8 + 2 * tc;
        {
            const int s_ = qt * 128 + r0;
            size_t idx = ((size_t)(b * Ss + s_)) * HIDn + hh * HD + d;
            *(__half2*)(g_O + idx) = __floats2half2_rn(o[nt][0] * i0, o[nt][1] * i0);
        }
        {
            const int s_ = qt * 128 + r0 + 8;
            size_t idx = ((size_t)(b * Ss + s_)) * HIDn + hh * HD + d;
            *(__half2*)(g_O + idx) = __floats2half2_rn(o[nt][2] * i1, o[nt][3] * i1);
        }
    }
}

// ============================================================================
// launch
// ============================================================================
extern "C" void kernel_launch(void* const* d_in, const int* in_sizes, int n_in,
                              void* d_out, int out_size)
{
    (void)in_sizes; (void)n_in; (void)out_size;
    const float* q  = (const float*)d_in[0];
    const float* k  = (const float*)d_in[1];
    const float* v  = (const float*)d_in[2];
    const float* wq = (const float*)d_in[3];
    const float* bq = (const float*)d_in[4];
    const float* wk = (const float*)d_in[5];
    const float* bk = (const float*)d_in[6];
    const float* wv = (const float*)d_in[7];
    const float* bv = (const float*)d_in[8];
    const float* wo = (const float*)d_in[9];
    const float* bo = (const float*)d_in[10];
    float* out = (float*)d_out;

    __half *Qp, *Kp, *Vp, *Op, *WTp, *Ap;
    cudaGetSymbolAddress((void**)&Qp,  g_Q);
    cudaGetSymbolAddress((void**)&Kp,  g_K);
    cudaGetSymbolAddress((void**)&Vp,  g_V);
    cudaGetSymbolAddress((void**)&Op,  g_O);
    cudaGetSymbolAddress((void**)&WTp, g_WT);
    cudaGetSymbolAddress((void**)&Ap,  g_A);

    cudaFuncSetAttribute(attn_kernel,
                         cudaFuncAttributeMaxDynamicSharedMemorySize, ATT_SMEM_BYTES);
    cudaFuncSetAttribute(gemm_tc<0>,
                         cudaFuncAttributeMaxDynamicSharedMemorySize, GEMM_SMEM);
    cudaFuncSetAttribute(gemm_tc<1>,
                         cudaFuncAttributeMaxDynamicSharedMemorySize, GEMM_SMEM);

    dim3 tgrid(32, 32), tblk(32, 8);
    dim3 ggrid(HIDn / 128, ROWS / 128);   // (8, 64)
    const int rblocks = ROWS * HIDn / 4 / 256;   // 8192

    transpose1024<<<tgrid, tblk>>>(wq, WTp);
    round_fp16<<<rblocks, 256>>>((const float4*)q, (__half2*)Ap);
    gemm_tc<1><<<ggrid, 256, GEMM_SMEM>>>(Ap, WTp, bq, Qp);

    transpose1024<<<tgrid, tblk>>>(wk, WTp);
    round_fp16<<<rblocks, 256>>>((const float4*)k, (__half2*)Ap);
    gemm_tc<1><<<ggrid, 256, GEMM_SMEM>>>(Ap, WTp, bk, Kp);

    transpose1024<<<tgrid, tblk>>>(wv, WTp);
    round_fp16<<<rblocks, 256>>>((const float4*)v, (__half2*)Ap);
    gemm_tc<1><<<ggrid, 256, GEMM_SMEM>>>(Ap, WTp, bv, Vp);

    attn_kernel<<<dim3(Ss / 128, Bb * HEADS), 256, ATT_SMEM_BYTES>>>();

    transpose1024<<<tgrid, tblk>>>(wo, WTp);
    gemm_tc<0><<<ggrid, 256, GEMM_SMEM>>>(Op, WTp, bo, out);
}

// round 9
// speedup vs baseline: 2.9821x; 1.0926x over previous
#include <cuda_runtime.h>
#include <cuda_fp16.h>
#include <math.h>
#include <stdint.h>

// Problem constants
#define Bb   4
#define Ss   2048
#define HIDn 1024
#define HEADS 16
#define HD   64
#define ROWS (Bb*Ss)          // 8192
#define QKV_STRIDE (Bb*HEADS*Ss*HD)   // 8388608

// softmax scale folded into Q: 0.125 * log2(e)
#define SCALE_Q 0.1803368801111244f

// ---------------- scratch (device globals: allocation-guard safe) ----------
__device__ __half g_QKV[3*QKV_STRIDE];   // [3][B,H,S,D] fp16 (Q pre-scaled)
__device__ __half g_O[Bb*Ss*HIDn];       // [B,S,H*D] fp16
__device__ __half g_WT4[4*HIDn*HIDn];    // 4 transposed+rounded weights [N][K]
__device__ __half g_A3[3*ROWS*HIDn];     // rounded activation copies

// ============================================================================
// helpers
// ============================================================================
__device__ __forceinline__ uint32_t smem_u32(const void* p) {
    uint32_t a;
    asm("{ .reg .u64 t; cvta.to.shared.u64 t, %1; cvt.u32.u64 %0, t; }"
        : "=r"(a) : "l"(p));
    return a;
}
__device__ __forceinline__ void mma16(float& d0, float& d1, float& d2, float& d3,
                                      uint32_t a0, uint32_t a1, uint32_t a2, uint32_t a3,
                                      uint32_t b0, uint32_t b1) {
    asm volatile(
        "mma.sync.aligned.m16n8k16.row.col.f32.f16.f16.f32 "
        "{%0,%1,%2,%3}, {%4,%5,%6,%7}, {%8,%9}, {%0,%1,%2,%3};"
        : "+f"(d0), "+f"(d1), "+f"(d2), "+f"(d3)
        : "r"(a0), "r"(a1), "r"(a2), "r"(a3), "r"(b0), "r"(b1));
}
__device__ __forceinline__ void ldm4(uint32_t& r0, uint32_t& r1, uint32_t& r2,
                                     uint32_t& r3, uint32_t addr) {
    asm volatile("ldmatrix.sync.aligned.m8n8.x4.shared.b16 {%0,%1,%2,%3}, [%4];"
                 : "=r"(r0), "=r"(r1), "=r"(r2), "=r"(r3) : "r"(addr));
}
__device__ __forceinline__ void ldm4t(uint32_t& r0, uint32_t& r1, uint32_t& r2,
                                      uint32_t& r3, uint32_t addr) {
    asm volatile("ldmatrix.sync.aligned.m8n8.x4.trans.shared.b16 {%0,%1,%2,%3}, [%4];"
                 : "=r"(r0), "=r"(r1), "=r"(r2), "=r"(r3) : "r"(addr));
}
__device__ __forceinline__ void cp16(uint32_t s, const void* g) {
    asm volatile("cp.async.cg.shared.global [%0], [%1], 16;" :: "r"(s), "l"(g));
}
__device__ __forceinline__ float ex2(float x) {
    float r;
    asm("ex2.approx.ftz.f32 %0, %1;" : "=f"(r) : "f"(x));
    return r;
}
#define CP_COMMIT() asm volatile("cp.async.commit_group;" ::: "memory")
#define CP_WAIT1()  asm volatile("cp.async.wait_group 1;"  ::: "memory")
#define CP_WAIT0()  asm volatile("cp.async.wait_group 0;"  ::: "memory")

// ============================================================================
// fp16 rounding prepass, 3 tensors in one launch (grid.y selects tensor)
// ============================================================================
__global__ __launch_bounds__(256)
void round_fp16_3(const float4* __restrict__ i0, const float4* __restrict__ i1,
                  const float4* __restrict__ i2, __half2* __restrict__ out)
{
    const int z = blockIdx.y;
    const float4* in = (z == 0) ? i0 : (z == 1) ? i1 : i2;
    const int i = blockIdx.x * 256 + threadIdx.x;
    float4 v = in[i];
    __half2* o = out + (size_t)z * (ROWS * HIDn / 2);
    o[2 * i]     = __floats2half2_rn(v.x, v.y);
    o[2 * i + 1] = __floats2half2_rn(v.z, v.w);
}

// ============================================================================
// Weight transpose + fp16 rounding, 4 weights in one launch (grid.z)
// ============================================================================
__global__ __launch_bounds__(256)
void transpose1024_4(const float* __restrict__ w0, const float* __restrict__ w1,
                     const float* __restrict__ w2, const float* __restrict__ w3,
                     __half* __restrict__ out4)
{
    __shared__ float t[32][33];
    const int z = blockIdx.z;
    const float* in = (z == 0) ? w0 : (z == 1) ? w1 : (z == 2) ? w2 : w3;
    __half* out = out4 + (size_t)z * HIDn * HIDn;
    int x = blockIdx.x * 32 + threadIdx.x;
    int y0 = blockIdx.y * 32;
    #pragma unroll
    for (int l = 0; l < 32; l += 8)
        t[threadIdx.y + l][threadIdx.x] = in[(size_t)(y0 + threadIdx.y + l) * 1024 + x];
    __syncthreads();
    int xo = blockIdx.y * 32 + threadIdx.x;
    int yo = blockIdx.x * 32;
    #pragma unroll
    for (int l = 0; l < 32; l += 8)
        out[(size_t)(yo + threadIdx.y + l) * 1024 + xo] =
            __float2half_rn(t[threadIdx.x][threadIdx.y + l]);
}

// ============================================================================
// fp16 mma.sync GEMM core (128x128 tile, BK=64, 3-stage cp.async, 2 CTAs/SM)
// ============================================================================
#define GSTR_B   144                   // bytes per smem row (64 halves + pad)
#define GSTG_B   (128*GSTR_B)          // 18432 bytes per stage per tensor
#define GEMM_SMEM (2*3*GSTG_B)         // 110592 bytes

struct GemmCore {
    uint32_t sA, sB;
    int tid, wid, lane, gr, tc, wm, wn;
    uint32_t aOff[4], bOff[2];
    int lr, lc;
    float acc[4][4][4];

    __device__ __forceinline__ void init(char* smc) {
        sA = smem_u32(smc);
        sB = sA + 3 * GSTG_B;
        tid = threadIdx.x; wid = tid >> 5; lane = tid & 31;
        gr = lane >> 2; tc = lane & 3;
        const int m8 = lane >> 3, e8 = lane & 7;
        wm = wid & 1; wn = wid >> 1;
        const int lrow = e8 + ((m8 & 1) << 3);
        const int lcolB = (m8 >> 1) << 4;
        #pragma unroll
        for (int mt = 0; mt < 4; mt++)
            aOff[mt] = (uint32_t)((wm * 64 + mt * 16 + lrow) * GSTR_B + lcolB);
        #pragma unroll
        for (int p = 0; p < 2; p++)
            bOff[p] = (uint32_t)((wn * 32 + p * 16 + lrow) * GSTR_B + lcolB);
        #pragma unroll
        for (int mt = 0; mt < 4; mt++)
            #pragma unroll
            for (int nt = 0; nt < 4; nt++)
                #pragma unroll
                for (int e = 0; e < 4; e++) acc[mt][nt][e] = 0.f;
        lr = tid >> 3; lc = tid & 7;
    }
    __device__ __forceinline__ void load_stage(int st, int chunk,
                                               const __half* Ag0, const __half* Bg0) {
        const __half* Ag = Ag0 + chunk * 64;
        const __half* Bg = Bg0 + chunk * 64;
        uint32_t aS = sA + st * GSTG_B;
        uint32_t bS = sB + st * GSTG_B;
        #pragma unroll
        for (int l = 0; l < 4; l++) {
            int r = lr + l * 32;
            cp16(aS + r * GSTR_B + lc * 16, Ag + (size_t)r * 1024 + lc * 8);
            cp16(bS + r * GSTR_B + lc * 16, Bg + (size_t)r * 1024 + lc * 8);
        }
    }
    __device__ __forceinline__ void run(const __half* Ag0, const __half* Bg0) {
        load_stage(0, 0, Ag0, Bg0); CP_COMMIT();
        load_stage(1, 1, Ag0, Bg0); CP_COMMIT();
        for (int i = 0; i < 16; i++) {
            const int s = i % 3;
            CP_WAIT1();
            __syncthreads();
            const int j = i + 2;
            if (j < 16) { load_stage(j % 3, j, Ag0, Bg0); }
            CP_COMMIT();
            const uint32_t aBs = sA + s * GSTG_B;
            const uint32_t bBs = sB + s * GSTG_B;
            #pragma unroll
            for (int ks = 0; ks < 4; ks++) {
                uint32_t a[4][4], b[4][2];
                #pragma unroll
                for (int mt = 0; mt < 4; mt++)
                    ldm4(a[mt][0], a[mt][1], a[mt][2], a[mt][3],
                         aBs + aOff[mt] + ks * 32);
                #pragma unroll
                for (int p = 0; p < 2; p++) {
                    uint32_t t0, t1, t2, t3;
                    ldm4(t0, t1, t2, t3, bBs + bOff[p] + ks * 32);
                    b[2 * p][0]     = t0; b[2 * p][1]     = t2;
                    b[2 * p + 1][0] = t1; b[2 * p + 1][1] = t3;
                }
                #pragma unroll
                for (int mt = 0; mt < 4; mt++)
                    #pragma unroll
                    for (int nt = 0; nt < 4; nt++)
                        mma16(acc[mt][nt][0], acc[mt][nt][1], acc[mt][nt][2], acc[mt][nt][3],
                              a[mt][0], a[mt][1], a[mt][2], a[mt][3], b[nt][0], b[nt][1]);
            }
        }
    }
};

// QKV projections fused: grid (8, 64, 3). z selects A slice, WT slice, bias,
// output slice. Q output (z=0) is pre-scaled by SCALE_Q for exp2-domain softmax.
__global__ __launch_bounds__(256, 2)
void gemm_qkv(const __half* __restrict__ A3, const __half* __restrict__ WT4,
              const float* __restrict__ bq, const float* __restrict__ bk,
              const float* __restrict__ bv, __half* __restrict__ QKV)
{
    extern __shared__ __align__(16) char smc[];
    const int z = blockIdx.z;
    const float* bias = (z == 0) ? bq : (z == 1) ? bk : bv;
    const float scale = (z == 0) ? SCALE_Q : 1.0f;
    const int row0 = blockIdx.y * 128;
    const int col0 = blockIdx.x * 128;

    GemmCore g; g.init(smc);
    g.run(A3  + (size_t)z * ROWS * HIDn + (size_t)row0 * 1024,
          WT4 + (size_t)z * HIDn * HIDn + (size_t)col0 * 1024);

    __half* C = QKV + (size_t)z * QKV_STRIDE;
    #pragma unroll
    for (int mt = 0; mt < 4; mt++) {
        const int r0 = row0 + g.wm * 64 + mt * 16 + g.gr;
        #pragma unroll
        for (int nt = 0; nt < 4; nt++) {
            const int c = col0 + g.wn * 32 + nt * 8 + 2 * g.tc;
            const float2 bi = *(const float2*)(bias + c);
            float v00 = (g.acc[mt][nt][0] + bi.x) * scale;
            float v01 = (g.acc[mt][nt][1] + bi.y) * scale;
            float v10 = (g.acc[mt][nt][2] + bi.x) * scale;
            float v11 = (g.acc[mt][nt][3] + bi.y) * scale;
            const int h = c >> 6, d = c & 63;
            {
                const int b = r0 >> 11, s_ = r0 & 2047;
                *(__half2*)(C + ((((size_t)(b * HEADS + h)) * Ss + s_) * HD + d))
                    = __floats2half2_rn(v00, v01);
            }
            {
                const int r1 = r0 + 8;
                const int b = r1 >> 11, s_ = r1 & 2047;
                *(__half2*)(C + ((((size_t)(b * HEADS + h)) * Ss + s_) * HD + d))
                    = __floats2half2_rn(v10, v11);
            }
        }
    }
}

// Output projection: C fp32 row-major.
__global__ __launch_bounds__(256, 2)
void gemm_out(const __half* __restrict__ A, const __half* __restrict__ WT,
              const float* __restrict__ bias, float* __restrict__ C)
{
    extern __shared__ __align__(16) char smc[];
    const int row0 = blockIdx.y * 128;
    const int col0 = blockIdx.x * 128;

    GemmCore g; g.init(smc);
    g.run(A + (size_t)row0 * 1024, WT + (size_t)col0 * 1024);

    #pragma unroll
    for (int mt = 0; mt < 4; mt++) {
        const int r0 = row0 + g.wm * 64 + mt * 16 + g.gr;
        #pragma unroll
        for (int nt = 0; nt < 4; nt++) {
            const int c = col0 + g.wn * 32 + nt * 8 + 2 * g.tc;
            const float2 bi = *(const float2*)(bias + c);
            *(float2*)(C + (size_t)r0 * 1024 + c) =
                make_float2(g.acc[mt][nt][0] + bi.x, g.acc[mt][nt][1] + bi.y);
            *(float2*)(C + (size_t)(r0 + 8) * 1024 + c) =
                make_float2(g.acc[mt][nt][2] + bi.x, g.acc[mt][nt][3] + bi.y);
        }
    }
}

// ============================================================================
// Flash attention, fp16 mma.sync, exp2-domain softmax (Q pre-scaled).
// Block = (bh, 128-query tile), 256 threads / 8 warps, 2 CTAs/SM.
// K/V double-buffered cp.async; P staged through per-warp smem for ldmatrix.
// ============================================================================
#define ASTR_B   144
#define ATILE_B  (128*ASTR_B)
#define KB_OFF   0
#define VB_OFF   (2*ATILE_B)
#define PS_OFF   (4*ATILE_B)
#define ATT_SMEM_BYTES (5*ATILE_B)          // 92160

__global__ __launch_bounds__(256, 2)
void attn_kernel()
{
    extern __shared__ __align__(16) char smc[];
    const uint32_t sBase = smem_u32(smc);
    const uint32_t sKB = sBase + KB_OFF;
    const uint32_t sVB = sBase + VB_OFF;
    const uint32_t sPS = sBase + PS_OFF;

    const int bh   = blockIdx.y;
    const int qt   = blockIdx.x;
    const int tid  = threadIdx.x;
    const int wid  = tid >> 5;
    const int lane = tid & 31;
    const int gr   = lane >> 2;
    const int tc   = lane & 3;
    const int m8   = lane >> 3;
    const int e8   = lane & 7;

    const __half* Qg = g_QKV + (size_t)bh * Ss * HD + (size_t)qt * 128 * HD;
    const __half* Kg = g_QKV + QKV_STRIDE     + (size_t)bh * Ss * HD;
    const __half* Vg = g_QKV + 2 * QKV_STRIDE + (size_t)bh * Ss * HD;

    const int lr = tid >> 3;
    const int lc = tid & 7;

    #define LOAD_KV(kt) do {                                                    \
        const __half* _Kt = Kg + (size_t)(kt) * 128 * HD;                       \
        const __half* _Vt = Vg + (size_t)(kt) * 128 * HD;                       \
        uint32_t _kS = sKB + ((kt) & 1) * ATILE_B;                              \
        uint32_t _vS = sVB + ((kt) & 1) * ATILE_B;                              \
        _Pragma("unroll")                                                       \
        for (int l = 0; l < 4; l++) {                                           \
            int r = lr + l * 32;                                                \
            cp16(_kS + r * ASTR_B + lc * 16, _Kt + (size_t)r * HD + lc * 8);    \
            cp16(_vS + r * ASTR_B + lc * 16, _Vt + (size_t)r * HD + lc * 8);    \
        }                                                                       \
    } while (0)

    LOAD_KV(0); CP_COMMIT();

    // stage Q (pre-scaled) into the P region, extract persistent fragments
    {
        __half* Pq = (__half*)(smc + PS_OFF);
        #pragma unroll
        for (int l = 0; l < 4; l++) {
            int r = lr + l * 32;
            *(uint4*)((char*)Pq + r * ASTR_B + lc * 16) =
                *(const uint4*)(Qg + (size_t)r * HD + lc * 8);
        }
    }
    __syncthreads();
    const int lrow = e8 + ((m8 & 1) << 3);
    const int lcolB = (m8 >> 1) << 4;
    uint32_t qf[4][4];
    {
        const uint32_t qbase = sPS + (uint32_t)((wid * 16 + lrow) * ASTR_B + lcolB);
        #pragma unroll
        for (int ks = 0; ks < 4; ks++)
            ldm4(qf[ks][0], qf[ks][1], qf[ks][2], qf[ks][3], qbase + ks * 32);
    }

    uint32_t kOff[4];
    #pragma unroll
    for (int p = 0; p < 4; p++)
        kOff[p] = (uint32_t)((p * 16 + lrow) * ASTR_B + lcolB);
    const uint32_t vOff = (uint32_t)(lrow * ASTR_B + lcolB);
    const uint32_t pLdBase = sPS + (uint32_t)(wid * 16 * ASTR_B + lrow * ASTR_B + lcolB);
    __half* pSt0 = (__half*)(smc + PS_OFF) + (wid * 16 + gr) * 72 + 2 * tc;
    __half* pSt1 = pSt0 + 8 * 72;

    float m0 = -1e30f, m1 = -1e30f, l0 = 0.f, l1 = 0.f;
    float o[8][4];
    #pragma unroll
    for (int nt = 0; nt < 8; nt++)
        #pragma unroll
        for (int e = 0; e < 4; e++) o[nt][e] = 0.f;

    for (int kt = 0; kt < 16; kt++) {
        CP_WAIT0();
        __syncthreads();

        if (kt < 15) { LOAD_KV(kt + 1); CP_COMMIT(); }

        const uint32_t kb = sKB + (kt & 1) * ATILE_B;
        const uint32_t vb = sVB + (kt & 1) * ATILE_B;

        #pragma unroll
        for (int h = 0; h < 2; h++) {
            // ---- S (exp2-domain scores) = Qscaled K^T for 64 keys ----
            float sacc[8][4];
            #pragma unroll
            for (int nt = 0; nt < 8; nt++)
                #pragma unroll
                for (int e = 0; e < 4; e++) sacc[nt][e] = 0.f;

            const uint32_t kbh = kb + h * (64 * ASTR_B);
            #pragma unroll
            for (int ks = 0; ks < 4; ks++) {
                #pragma unroll
                for (int p = 0; p < 4; p++) {
                    uint32_t t0, t1, t2, t3;
                    ldm4(t0, t1, t2, t3, kbh + kOff[p] + ks * 32);
                    mma16(sacc[2 * p][0], sacc[2 * p][1], sacc[2 * p][2], sacc[2 * p][3],
                          qf[ks][0], qf[ks][1], qf[ks][2], qf[ks][3], t0, t2);
                    mma16(sacc[2 * p + 1][0], sacc[2 * p + 1][1],
                          sacc[2 * p + 1][2], sacc[2 * p + 1][3],
                          qf[ks][0], qf[ks][1], qf[ks][2], qf[ks][3], t1, t3);
                }
            }

            // ---- register softmax in exp2 domain (rows gr, gr+8) ----
            float mx0 = -1e30f, mx1 = -1e30f;
            #pragma unroll
            for (int nt = 0; nt < 8; nt++) {
                mx0 = fmaxf(mx0, fmaxf(sacc[nt][0], sacc[nt][1]));
                mx1 = fmaxf(mx1, fmaxf(sacc[nt][2], sacc[nt][3]));
            }
            mx0 = fmaxf(mx0, __shfl_xor_sync(0xFFFFFFFFu, mx0, 1));
            mx0 = fmaxf(mx0, __shfl_xor_sync(0xFFFFFFFFu, mx0, 2));
            mx1 = fmaxf(mx1, __shfl_xor_sync(0xFFFFFFFFu, mx1, 1));
            mx1 = fmaxf(mx1, __shfl_xor_sync(0xFFFFFFFFu, mx1, 2));
            const float mn0 = fmaxf(m0, mx0), mn1 = fmaxf(m1, mx1);
            const float c0 = ex2(m0 - mn0), c1 = ex2(m1 - mn1);
            float s0 = 0.f, s1 = 0.f;
            #pragma unroll
            for (int nt = 0; nt < 8; nt++) {
                sacc[nt][0] = ex2(sacc[nt][0] - mn0);
                sacc[nt][1] = ex2(sacc[nt][1] - mn0);
                sacc[nt][2] = ex2(sacc[nt][2] - mn1);
                sacc[nt][3] = ex2(sacc[nt][3] - mn1);
                s0 += sacc[nt][0] + sacc[nt][1];
                s1 += sacc[nt][2] + sacc[nt][3];
            }
            s0 += __shfl_xor_sync(0xFFFFFFFFu, s0, 1);
            s0 += __shfl_xor_sync(0xFFFFFFFFu, s0, 2);
            s1 += __shfl_xor_sync(0xFFFFFFFFu, s1, 1);
            s1 += __shfl_xor_sync(0xFFFFFFFFu, s1, 2);
            l0 = l0 * c0 + s0;  l1 = l1 * c1 + s1;
            m0 = mn0;           m1 = mn1;
            #pragma unroll
            for (int nt = 0; nt < 8; nt++) {
                o[nt][0] *= c0; o[nt][1] *= c0;
                o[nt][2] *= c1; o[nt][3] *= c1;
            }

            // ---- stage P as fp16 into warp-private smem ----
            #pragma unroll
            for (int nt = 0; nt < 8; nt++) {
                *(__half2*)(pSt0 + nt * 8) = __floats2half2_rn(sacc[nt][0], sacc[nt][1]);
                *(__half2*)(pSt1 + nt * 8) = __floats2half2_rn(sacc[nt][2], sacc[nt][3]);
            }
            __syncwarp();

            // ---- o += P V for this half ----
            const uint32_t vbh = vb + h * (64 * ASTR_B);
            #pragma unroll
            for (int kp = 0; kp < 4; kp++) {
                uint32_t a0, a1, a2, a3;
                ldm4(a0, a1, a2, a3, pLdBase + kp * 32);
                #pragma unroll
                for (int np = 0; np < 4; np++) {
                    uint32_t t0, t1, t2, t3;
                    ldm4t(t0, t1, t2, t3, vbh + vOff + kp * (16 * ASTR_B) + np * 32);
                    mma16(o[2 * np][0], o[2 * np][1], o[2 * np][2], o[2 * np][3],
                          a0, a1, a2, a3, t0, t1);
                    mma16(o[2 * np + 1][0], o[2 * np + 1][1],
                          o[2 * np + 1][2], o[2 * np + 1][3],
                          a0, a1, a2, a3, t2, t3);
                }
            }
        }
    }

    // ---- normalize + store to g_O [B,S,H*D] fp16 ----
    const float i0 = 1.0f / l0;
    const float i1 = 1.0f / l1;
    const int b  = bh >> 4;
    const int hh = bh & 15;
    const int r0 = wid * 16 + gr;
    #pragma unroll
    for (int nt = 0; nt < 8; nt++) {
        const int d = nt * 8 + 2 * tc;
        {
            const int s_ = qt * 128 + r0;
            size_t idx = ((size_t)(b * Ss + s_)) * HIDn + hh * HD + d;
            *(__half2*)(g_O + idx) = __floats2half2_rn(o[nt][0] * i0, o[nt][1] * i0);
        }
        {
            const int s_ = qt * 128 + r0 + 8;
            size_t idx = ((size_t)(b * Ss + s_)) * HIDn + hh * HD + d;
            *(__half2*)(g_O + idx) = __floats2half2_rn(o[nt][2] * i1, o[nt][3] * i1);
        }
    }
}

// ============================================================================
// launch
// ============================================================================
extern "C" void kernel_launch(void* const* d_in, const int* in_sizes, int n_in,
                              void* d_out, int out_size)
{
    (void)in_sizes; (void)n_in; (void)out_size;
    const float* q  = (const float*)d_in[0];
    const float* k  = (const float*)d_in[1];
    const float* v  = (const float*)d_in[2];
    const float* wq = (const float*)d_in[3];
    const float* bq = (const float*)d_in[4];
    const float* wk = (const float*)d_in[5];
    const float* bk = (const float*)d_in[6];
    const float* wv = (const float*)d_in[7];
    const float* bv = (const float*)d_in[8];
    const float* wo = (const float*)d_in[9];
    const float* bo = (const float*)d_in[10];
    float* out = (float*)d_out;

    __half *QKVp, *Op, *WT4p, *A3p;
    cudaGetSymbolAddress((void**)&QKVp, g_QKV);
    cudaGetSymbolAddress((void**)&Op,   g_O);
    cudaGetSymbolAddress((void**)&WT4p, g_WT4);
    cudaGetSymbolAddress((void**)&A3p,  g_A3);

    cudaFuncSetAttribute(attn_kernel,
                         cudaFuncAttributeMaxDynamicSharedMemorySize, ATT_SMEM_BYTES);
    cudaFuncSetAttribute(gemm_qkv,
                         cudaFuncAttributeMaxDynamicSharedMemorySize, GEMM_SMEM);
    cudaFuncSetAttribute(gemm_out,
                         cudaFuncAttributeMaxDynamicSharedMemorySize, GEMM_SMEM);

    const int rblocks = ROWS * HIDn / 4 / 256;   // 8192

    // prep: 4 weight transposes + 3 activation roundings (2 launches)
    transpose1024_4<<<dim3(32, 32, 4), dim3(32, 8)>>>(wq, wk, wv, wo, WT4p);
    round_fp16_3<<<dim3(rblocks, 3), 256>>>((const float4*)q, (const float4*)k,
                                            (const float4*)v, (__half2*)A3p);

    // fused QKV projections (Q pre-scaled for exp2 softmax)
    gemm_qkv<<<dim3(8, 64, 3), 256, GEMM_SMEM>>>(A3p, WT4p, bq, bk, bv, QKVp);

    attn_kernel<<<dim3(Ss / 128, Bb * HEADS), 256, ATT_SMEM_BYTES>>>();

    gemm_out<<<dim3(8, 64), 256, GEMM_SMEM>>>(Op, WT4p + 3 * (size_t)HIDn * HIDn,
                                              bo, out);
}